// round 2
// baseline (speedup 1.0000x reference)
#include <cuda_runtime.h>
#include <cuda_bf16.h>
#include <math.h>

// ---------------------------------------------------------------------------
// Fixed problem shape (from reference setup_inputs)
// ---------------------------------------------------------------------------
#define D_MODEL 1024
#define HEADS   16
#define HEAD_DIM 64
#define FF_DIM  4096
#define SEQ_L   2048
#define EPS     1e-5f
#define MROWS   4096      // B * L = 2 * 2048

// ---------------------------------------------------------------------------
// Scratch (static device globals; no runtime allocation allowed)
// ---------------------------------------------------------------------------
__device__ float g_q   [MROWS * D_MODEL];
__device__ float g_k   [MROWS * D_MODEL];
__device__ float g_v   [MROWS * D_MODEL];
__device__ float g_attn[MROWS * D_MODEL];
__device__ float g_proj[MROWS * D_MODEL];
__device__ float g_h   [MROWS * D_MODEL];
__device__ float g_ff  [MROWS * FF_DIM];
__device__ float g_tmp [MROWS * D_MODEL];

// ---------------------------------------------------------------------------
// SGEMM: C[M,N] = A[M,K] @ B[K,N] + bias[N]  (optional ReLU)
// 128x128 block tile, BK=8, 256 threads, 8x8 microtile per thread.
// All dims are multiples of 128 / 8 here, so no bounds checks.
// ---------------------------------------------------------------------------
#define GBM 128
#define GBN 128
#define GBK 8

__global__ __launch_bounds__(256) void sgemm_kernel(
    const float* __restrict__ A, const float* __restrict__ B,
    const float* __restrict__ bias, float* __restrict__ C,
    int M, int N, int K, int relu)
{
    __shared__ float As[GBK][GBM];
    __shared__ float Bs[GBK][GBN];

    const int tid = threadIdx.x;
    const int row0 = blockIdx.y * GBM;
    const int col0 = blockIdx.x * GBN;

    // global loads: 1 float4 of A and 1 float4 of B per thread per K-step
    const int a_row = tid >> 1;           // 0..127
    const int a_col = (tid & 1) * 4;      // 0 or 4
    const int b_row = tid >> 5;           // 0..7
    const int b_col = (tid & 31) * 4;     // 0..124

    const int tx = tid & 15;              // 0..15 -> cols tx*8
    const int ty = tid >> 4;              // 0..15 -> rows ty*8

    const float* Aptr = A + (size_t)(row0 + a_row) * K + a_col;
    const float* Bptr = B + (size_t)b_row * N + col0 + b_col;

    float acc[8][8];
#pragma unroll
    for (int i = 0; i < 8; i++)
#pragma unroll
        for (int j = 0; j < 8; j++) acc[i][j] = 0.f;

    for (int k0 = 0; k0 < K; k0 += GBK) {
        float4 av = *(const float4*)(Aptr + k0);
        float4 bv = *(const float4*)(Bptr + (size_t)k0 * N);
        __syncthreads();
        As[a_col + 0][a_row] = av.x;
        As[a_col + 1][a_row] = av.y;
        As[a_col + 2][a_row] = av.z;
        As[a_col + 3][a_row] = av.w;
        *(float4*)&Bs[b_row][b_col] = bv;
        __syncthreads();

#pragma unroll
        for (int kk = 0; kk < GBK; kk++) {
            float a[8], b[8];
            *(float4*)&a[0] = *(const float4*)&As[kk][ty * 8 + 0];
            *(float4*)&a[4] = *(const float4*)&As[kk][ty * 8 + 4];
            *(float4*)&b[0] = *(const float4*)&Bs[kk][tx * 8 + 0];
            *(float4*)&b[4] = *(const float4*)&Bs[kk][tx * 8 + 4];
#pragma unroll
            for (int i = 0; i < 8; i++)
#pragma unroll
                for (int j = 0; j < 8; j++)
                    acc[i][j] = fmaf(a[i], b[j], acc[i][j]);
        }
    }

    // epilogue: bias (+ReLU), store
    float bb[8];
#pragma unroll
    for (int j = 0; j < 8; j++) bb[j] = bias[col0 + tx * 8 + j];

#pragma unroll
    for (int i = 0; i < 8; i++) {
        float* cp = C + (size_t)(row0 + ty * 8 + i) * N + col0 + tx * 8;
        float out[8];
#pragma unroll
        for (int j = 0; j < 8; j++) {
            float vv = acc[i][j] + bb[j];
            out[j] = relu ? fmaxf(vv, 0.f) : vv;
        }
        *(float4*)&cp[0] = *(float4*)&out[0];
        *(float4*)&cp[4] = *(float4*)&out[4];
    }
}

// ---------------------------------------------------------------------------
// Flash-attention (fp32, non-causal). One block = (b,h, 64 query rows).
// smem: Qt[64][64] (d-major), KP[64][64] (K^T, later reused for P^T),
//       Vs[64][64]. Exactly 48 KB.
// Thread layout: 256 threads, (tr,tc) each owns 4 rows x 4 cols.
// ---------------------------------------------------------------------------
__global__ __launch_bounds__(256) void attn_kernel(
    const float* __restrict__ q, const float* __restrict__ k,
    const float* __restrict__ v, float* __restrict__ o, int L)
{
    __shared__ float Qt[64][64];   // [d][row]
    __shared__ float KP[64][64];   // K^T: [d][key]  ->  P^T: [key][row]
    __shared__ float Vs[64][64];   // [key][d]

    const int bh = blockIdx.y;
    const int b  = bh / HEADS;
    const int h  = bh % HEADS;
    const int l0 = blockIdx.x * 64;
    const int tid = threadIdx.x;
    const int tr = tid >> 4, tc = tid & 15;
    const int r0 = tr * 4, c0 = tc * 4;

    const size_t base = ((size_t)b * L) * D_MODEL + h * HEAD_DIM;

    // load Q tile (transposed into Qt)
    for (int i = tid; i < 64 * 16; i += 256) {
        int rr = i >> 4;
        int cc = (i & 15) * 4;
        float4 qv = *(const float4*)(q + base + (size_t)(l0 + rr) * D_MODEL + cc);
        Qt[cc + 0][rr] = qv.x; Qt[cc + 1][rr] = qv.y;
        Qt[cc + 2][rr] = qv.z; Qt[cc + 3][rr] = qv.w;
    }

    float m_i[4], l_i[4], acc[4][4];
#pragma unroll
    for (int i = 0; i < 4; i++) {
        m_i[i] = -3.0e38f; l_i[i] = 0.f;
#pragma unroll
        for (int j = 0; j < 4; j++) acc[i][j] = 0.f;
    }

    for (int s0 = 0; s0 < L; s0 += 64) {
        __syncthreads();   // previous-iteration smem reads done
        for (int i = tid; i < 64 * 16; i += 256) {
            int rr = i >> 4;
            int cc = (i & 15) * 4;
            float4 kv = *(const float4*)(k + base + (size_t)(s0 + rr) * D_MODEL + cc);
            KP[cc + 0][rr] = kv.x; KP[cc + 1][rr] = kv.y;
            KP[cc + 2][rr] = kv.z; KP[cc + 3][rr] = kv.w;
            float4 vv = *(const float4*)(v + base + (size_t)(s0 + rr) * D_MODEL + cc);
            *(float4*)&Vs[rr][cc] = vv;
        }
        __syncthreads();

        // S = Q @ K^T  (4x4 per thread)
        float s[4][4];
#pragma unroll
        for (int i = 0; i < 4; i++)
#pragma unroll
            for (int j = 0; j < 4; j++) s[i][j] = 0.f;
        for (int kk = 0; kk < 64; kk++) {
            float4 qv = *(const float4*)&Qt[kk][r0];
            float4 kv = *(const float4*)&KP[kk][c0];
            float qa[4] = {qv.x, qv.y, qv.z, qv.w};
            float ka[4] = {kv.x, kv.y, kv.z, kv.w};
#pragma unroll
            for (int i = 0; i < 4; i++)
#pragma unroll
                for (int j = 0; j < 4; j++)
                    s[i][j] = fmaf(qa[i], ka[j], s[i][j]);
        }

        // online softmax update (scale = 1/sqrt(64) = 0.125)
        float p[4][4];
#pragma unroll
        for (int i = 0; i < 4; i++) {
            float tmax = -3.0e38f;
#pragma unroll
            for (int j = 0; j < 4; j++) {
                s[i][j] *= 0.125f;
                tmax = fmaxf(tmax, s[i][j]);
            }
#pragma unroll
            for (int off = 1; off < 16; off <<= 1)
                tmax = fmaxf(tmax, __shfl_xor_sync(0xffffffffu, tmax, off));
            float mnew = fmaxf(m_i[i], tmax);
            float corr = __expf(m_i[i] - mnew);
            l_i[i] *= corr;
#pragma unroll
            for (int j = 0; j < 4; j++) acc[i][j] *= corr;
            float rs = 0.f;
#pragma unroll
            for (int j = 0; j < 4; j++) {
                p[i][j] = __expf(s[i][j] - mnew);
                rs += p[i][j];
            }
#pragma unroll
            for (int off = 1; off < 16; off <<= 1)
                rs += __shfl_xor_sync(0xffffffffu, rs, off);
            l_i[i] += rs;
            m_i[i] = mnew;
        }

        __syncthreads();   // done reading KP as K^T
        // store P^T into KP: KP[key][row]
#pragma unroll
        for (int i = 0; i < 4; i++)
#pragma unroll
            for (int j = 0; j < 4; j++)
                KP[c0 + j][r0 + i] = p[i][j];
        __syncthreads();

        // acc += P @ V
        for (int ss = 0; ss < 64; ss++) {
            float4 pv = *(const float4*)&KP[ss][r0];
            float4 vv = *(const float4*)&Vs[ss][c0];
            float pa[4] = {pv.x, pv.y, pv.z, pv.w};
            float va[4] = {vv.x, vv.y, vv.z, vv.w};
#pragma unroll
            for (int i = 0; i < 4; i++)
#pragma unroll
                for (int j = 0; j < 4; j++)
                    acc[i][j] = fmaf(pa[i], va[j], acc[i][j]);
        }
    }

    // write O = acc / l
#pragma unroll
    for (int i = 0; i < 4; i++) {
        float inv = 1.f / l_i[i];
#pragma unroll
        for (int j = 0; j < 4; j++)
            o[base + (size_t)(l0 + r0 + i) * D_MODEL + c0 + j] = acc[i][j] * inv;
    }
}

// ---------------------------------------------------------------------------
// Fused residual + LayerNorm: out = LN(a + r) * g + beta.  One block per row.
// 256 threads x 4 elems = 1024 cols.
// ---------------------------------------------------------------------------
__global__ __launch_bounds__(256) void ln_residual_kernel(
    const float* __restrict__ a, const float* __restrict__ r,
    const float* __restrict__ g, const float* __restrict__ beta,
    float* __restrict__ out)
{
    __shared__ float red[8];
    const int row = blockIdx.x;
    const int tid = threadIdx.x;
    const int lane = tid & 31, warp = tid >> 5;
    const size_t off = (size_t)row * D_MODEL + tid * 4;

    float4 va = *(const float4*)(a + off);
    float4 vr = *(const float4*)(r + off);
    float x[4] = {va.x + vr.x, va.y + vr.y, va.z + vr.z, va.w + vr.w};

    float sum = x[0] + x[1] + x[2] + x[3];
#pragma unroll
    for (int o = 16; o; o >>= 1) sum += __shfl_down_sync(0xffffffffu, sum, o);
    if (lane == 0) red[warp] = sum;
    __syncthreads();
    if (warp == 0) {
        float v = (lane < 8) ? red[lane] : 0.f;
#pragma unroll
        for (int o = 4; o; o >>= 1) v += __shfl_down_sync(0xffu, v, o);
        if (lane == 0) red[0] = v;
    }
    __syncthreads();
    const float mu = red[0] * (1.f / D_MODEL);
    __syncthreads();

    float sq = 0.f;
#pragma unroll
    for (int i = 0; i < 4; i++) {
        float d = x[i] - mu;
        sq += d * d;
    }
#pragma unroll
    for (int o = 16; o; o >>= 1) sq += __shfl_down_sync(0xffffffffu, sq, o);
    if (lane == 0) red[warp] = sq;
    __syncthreads();
    if (warp == 0) {
        float v = (lane < 8) ? red[lane] : 0.f;
#pragma unroll
        for (int o = 4; o; o >>= 1) v += __shfl_down_sync(0xffu, v, o);
        if (lane == 0) red[0] = v;
    }
    __syncthreads();
    const float rstd = rsqrtf(red[0] * (1.f / D_MODEL) + EPS);

    float4 gg = *(const float4*)(g + tid * 4);
    float4 bb = *(const float4*)(beta + tid * 4);
    float ga[4] = {gg.x, gg.y, gg.z, gg.w};
    float ba[4] = {bb.x, bb.y, bb.z, bb.w};
    float y[4];
#pragma unroll
    for (int i = 0; i < 4; i++)
        y[i] = (x[i] - mu) * rstd * ga[i] + ba[i];
    *(float4*)(out + off) = *(float4*)&y[0];
}

// ---------------------------------------------------------------------------
// Launch sequence
// ---------------------------------------------------------------------------
extern "C" void kernel_launch(void* const* d_in, const int* in_sizes, int n_in,
                              void* d_out, int out_size)
{
    const float* x  = (const float*)d_in[0];
    const float* Wq = (const float*)d_in[1];
    const float* bq = (const float*)d_in[2];
    const float* Wk = (const float*)d_in[3];
    const float* bk = (const float*)d_in[4];
    const float* Wv = (const float*)d_in[5];
    const float* bv = (const float*)d_in[6];
    const float* Wm = (const float*)d_in[7];
    const float* bm = (const float*)d_in[8];
    const float* W1 = (const float*)d_in[9];
    const float* b1 = (const float*)d_in[10];
    const float* W2 = (const float*)d_in[11];
    const float* b2 = (const float*)d_in[12];
    const float* g1  = (const float*)d_in[13];
    const float* be1 = (const float*)d_in[14];
    const float* g2  = (const float*)d_in[15];
    const float* be2 = (const float*)d_in[16];
    float* out = (float*)d_out;

    const int M = in_sizes[0] / D_MODEL;   // 4096
    const int L = SEQ_L;
    const int B = M / L;

    float *q, *k, *v, *attn, *proj, *h, *ff, *tmp;
    cudaGetSymbolAddress((void**)&q,    g_q);
    cudaGetSymbolAddress((void**)&k,    g_k);
    cudaGetSymbolAddress((void**)&v,    g_v);
    cudaGetSymbolAddress((void**)&attn, g_attn);
    cudaGetSymbolAddress((void**)&proj, g_proj);
    cudaGetSymbolAddress((void**)&h,    g_h);
    cudaGetSymbolAddress((void**)&ff,   g_ff);
    cudaGetSymbolAddress((void**)&tmp,  g_tmp);

    dim3 blk(256);
    dim3 grid_d(D_MODEL / GBN, M / GBM);   // (8, 32)
    dim3 grid_f(FF_DIM / GBN,  M / GBM);   // (32, 32)

    // QKV projections
    sgemm_kernel<<<grid_d, blk>>>(x, Wq, bq, q, M, D_MODEL, D_MODEL, 0);
    sgemm_kernel<<<grid_d, blk>>>(x, Wk, bk, k, M, D_MODEL, D_MODEL, 0);
    sgemm_kernel<<<grid_d, blk>>>(x, Wv, bv, v, M, D_MODEL, D_MODEL, 0);

    // attention
    dim3 agrid(L / 64, B * HEADS);         // (32, 32)
    attn_kernel<<<agrid, blk>>>(q, k, v, attn, L);

    // output projection + residual LN
    sgemm_kernel<<<grid_d, blk>>>(attn, Wm, bm, proj, M, D_MODEL, D_MODEL, 0);
    ln_residual_kernel<<<M, blk>>>(x, proj, g1, be1, h);

    // FFN
    sgemm_kernel<<<grid_f, blk>>>(h, W1, b1, ff, M, FF_DIM, D_MODEL, 1);
    sgemm_kernel<<<grid_d, blk>>>(ff, W2, b2, tmp, M, D_MODEL, FF_DIM, 0);
    ln_residual_kernel<<<M, blk>>>(h, tmp, g2, be2, out);
}

// round 4
// speedup vs baseline: 1.6103x; 1.6103x over previous
#include <cuda_runtime.h>
#include <cuda_bf16.h>
#include <math.h>
#include <stdint.h>

// ---------------------------------------------------------------------------
// Fixed problem shape
// ---------------------------------------------------------------------------
#define D_MODEL 1024
#define HEADS   16
#define HEAD_DIM 64
#define FF_DIM  4096
#define SEQ_L   2048
#define EPS     1e-5f
#define MROWS   4096      // B * L

// ---------------------------------------------------------------------------
// Scratch (static device globals; no runtime allocation allowed)
// ---------------------------------------------------------------------------
__device__ float g_q   [MROWS * D_MODEL];
__device__ float g_k   [MROWS * D_MODEL];
__device__ float g_v   [MROWS * D_MODEL];
__device__ float g_attn[MROWS * D_MODEL];
__device__ float g_proj[MROWS * D_MODEL];
__device__ float g_h   [MROWS * D_MODEL];
__device__ float g_ff  [MROWS * FF_DIM];
__device__ float g_tmp [MROWS * D_MODEL];

// weight transposed+split scratch: [N][K] bf16 hi / lo
__device__ __nv_bfloat16 g_wq_h[D_MODEL * D_MODEL];
__device__ __nv_bfloat16 g_wq_l[D_MODEL * D_MODEL];
__device__ __nv_bfloat16 g_wk_h[D_MODEL * D_MODEL];
__device__ __nv_bfloat16 g_wk_l[D_MODEL * D_MODEL];
__device__ __nv_bfloat16 g_wv_h[D_MODEL * D_MODEL];
__device__ __nv_bfloat16 g_wv_l[D_MODEL * D_MODEL];
__device__ __nv_bfloat16 g_wm_h[D_MODEL * D_MODEL];
__device__ __nv_bfloat16 g_wm_l[D_MODEL * D_MODEL];
__device__ __nv_bfloat16 g_w1_h[D_MODEL * FF_DIM];
__device__ __nv_bfloat16 g_w1_l[D_MODEL * FF_DIM];
__device__ __nv_bfloat16 g_w2_h[FF_DIM * D_MODEL];
__device__ __nv_bfloat16 g_w2_l[FF_DIM * D_MODEL];

// ---------------------------------------------------------------------------
// Helpers (base sm_100-safe: ldmatrix + mma.sync only, NO tcgen05)
// ---------------------------------------------------------------------------
__device__ __forceinline__ uint32_t smem_u32(const void* p) {
    uint32_t a;
    asm("{ .reg .u64 t; cvta.to.shared.u64 t, %1; cvt.u32.u64 %0, t; }" : "=r"(a) : "l"(p));
    return a;
}

__device__ __forceinline__ void ldsm4(uint32_t* r, uint32_t addr) {
    asm volatile("ldmatrix.sync.aligned.m8n8.x4.shared.b16 {%0,%1,%2,%3}, [%4];"
                 : "=r"(r[0]), "=r"(r[1]), "=r"(r[2]), "=r"(r[3]) : "r"(addr));
}

__device__ __forceinline__ void mma16816(float* d, const uint32_t* a, const uint32_t* b) {
    asm volatile("mma.sync.aligned.m16n8k16.row.col.f32.bf16.bf16.f32 "
                 "{%0,%1,%2,%3}, {%4,%5,%6,%7}, {%8,%9}, {%0,%1,%2,%3};"
                 : "+f"(d[0]), "+f"(d[1]), "+f"(d[2]), "+f"(d[3])
                 : "r"(a[0]), "r"(a[1]), "r"(a[2]), "r"(a[3]), "r"(b[0]), "r"(b[1]));
}

__device__ __forceinline__ void sts_v2(uint32_t addr, uint32_t a, uint32_t b) {
    asm volatile("st.shared.v2.b32 [%0], {%1, %2};" :: "r"(addr), "r"(a), "r"(b) : "memory");
}
__device__ __forceinline__ void sts_v4(uint32_t addr, uint4 v) {
    asm volatile("st.shared.v4.b32 [%0], {%1, %2, %3, %4};"
                 :: "r"(addr), "r"(v.x), "r"(v.y), "r"(v.z), "r"(v.w) : "memory");
}

// ---------------------------------------------------------------------------
// Weight transpose + hi/lo bf16 split: W[K,N] fp32 -> Th/Tl[N,K] bf16
// ---------------------------------------------------------------------------
__global__ __launch_bounds__(256) void transpose_split_kernel(
    const float* __restrict__ W, __nv_bfloat16* __restrict__ Th,
    __nv_bfloat16* __restrict__ Tl, int K, int N)
{
    __shared__ float t[32][33];
    const int n0 = blockIdx.x * 32, k0 = blockIdx.y * 32;
    const int tx = threadIdx.x & 31, ty = threadIdx.x >> 5;   // 32 x 8
#pragma unroll
    for (int i = 0; i < 4; i++)
        t[ty + i * 8][tx] = W[(size_t)(k0 + ty + i * 8) * N + n0 + tx];
    __syncthreads();
#pragma unroll
    for (int i = 0; i < 4; i++) {
        float v = t[tx][ty + i * 8];
        __nv_bfloat16 h = __float2bfloat16(v);
        __nv_bfloat16 l = __float2bfloat16(v - __bfloat162float(h));
        size_t o = (size_t)(n0 + ty + i * 8) * K + k0 + tx;
        Th[o] = h;
        Tl[o] = l;
    }
}

// ---------------------------------------------------------------------------
// HMMA GEMM: C[M,N] = A[M,K] (fp32, split on the fly) @ BT[N,K] (pre-split
// bf16 hi/lo) + bias, optional ReLU.
// 128x128 CTA tile, BK=32, 256 threads (8 warps in 4Mx2N -> 32x64 warp tile).
// SMEM rows = 128B = [hi 64B | lo 64B], SW128 swizzle, double buffered.
// Split-3 MMA: AhBh + AhBl + AlBh, fp32 accumulate.
// ---------------------------------------------------------------------------
#define TBK 32
#define STAGE_BYTES 32768                 // A 16KB + B 16KB
#define GEMM_SMEM_BYTES (2 * STAGE_BYTES) // 64KB

__global__ __launch_bounds__(256, 1)
void gemm_tc_kernel(const float* __restrict__ A,
                    const __nv_bfloat16* __restrict__ BTh,
                    const __nv_bfloat16* __restrict__ BTl,
                    const float* __restrict__ bias, float* __restrict__ C,
                    int M, int N, int K, int relu)
{
    extern __shared__ char smem[];
    const uint32_t sb = smem_u32(smem);

    const int tid = threadIdx.x;
    const int wid = tid >> 5;
    const int lane = tid & 31;
    const int row0 = blockIdx.y * 128;
    const int col0 = blockIdx.x * 128;
    const int wm0 = (wid & 3) * 32;       // warp M offset in tile
    const int wn0 = (wid >> 2) * 64;      // warp N offset in tile
    const int nkb = K / TBK;

    // ---- staging source coordinates (per thread, fixed) ----
    const int ac4 = (tid & 7) * 4;        // A k-col (floats), 0..28
    const int ar  = tid >> 3;             // A base row (+ it*32)
    const int bc  = tid & 7;              // B chunk 0..7 (0-3 hi, 4-7 lo)
    const int bn  = tid >> 3;             // B base n-row (+ it*32)
    const __nv_bfloat16* Bsrc = (bc < 4) ? BTh : BTl;
    const int bck = (bc & 3) * 8;         // k offset (bf16) within k-block

    // ---- compute-lane coordinates ----
    const int lr = lane & 7;
    const int mh = (lane >> 3) & 1;       // A: row half     | B: k-chunk bit
    const int kh = (lane >> 4) & 1;       // A: k-chunk bit  | B: n half
    uint32_t aRow[2], bN[4];
#pragma unroll
    for (int mt = 0; mt < 2; mt++) aRow[mt] = wm0 + mt * 16 + mh * 8 + lr;
#pragma unroll
    for (int g = 0; g < 4; g++)    bN[g]   = wn0 + g * 16 + kh * 8 + lr;

    float acc[2][8][4];
#pragma unroll
    for (int mt = 0; mt < 2; mt++)
#pragma unroll
        for (int nt = 0; nt < 8; nt++)
#pragma unroll
            for (int i = 0; i < 4; i++) acc[mt][nt][i] = 0.f;

    float4 pa[4];
    uint4  pb[4];

    // ---- global load of k-block kb into registers ----
    auto gload = [&](int kb) {
#pragma unroll
        for (int it = 0; it < 4; it++) {
            pa[it] = *(const float4*)(A + (size_t)(row0 + ar + it * 32) * K + kb * TBK + ac4);
            pb[it] = *(const uint4*)((const char*)Bsrc +
                       ((size_t)(col0 + bn + it * 32) * K + kb * TBK + bck) * 2);
        }
    };
    // ---- write registers to smem stage s (split A, swizzle) ----
    auto swrite = [&](int s) {
        const uint32_t Ab = sb + s * STAGE_BYTES;
        const uint32_t Bb = Ab + 16384;
        const int achunk = ac4 >> 3;            // 0..3
        const int awithin = (ac4 & 7) * 2;      // 0 or 8
#pragma unroll
        for (int it = 0; it < 4; it++) {
            const int r = ar + it * 32;
            float4 v = pa[it];
            __nv_bfloat162 h0 = __float22bfloat162_rn(make_float2(v.x, v.y));
            __nv_bfloat162 h1 = __float22bfloat162_rn(make_float2(v.z, v.w));
            float2 f0 = __bfloat1622float2(h0);
            float2 f1 = __bfloat1622float2(h1);
            __nv_bfloat162 l0 = __float22bfloat162_rn(make_float2(v.x - f0.x, v.y - f0.y));
            __nv_bfloat162 l1 = __float22bfloat162_rn(make_float2(v.z - f1.x, v.w - f1.y));
            const int sw = r & 7;
            sts_v2(Ab + r * 128 + (((achunk    ) ^ sw) << 4) + awithin,
                   *(uint32_t*)&h0, *(uint32_t*)&h1);
            sts_v2(Ab + r * 128 + (((achunk + 4) ^ sw) << 4) + awithin,
                   *(uint32_t*)&l0, *(uint32_t*)&l1);
            const int n = bn + it * 32;
            sts_v4(Bb + n * 128 + ((bc ^ (n & 7)) << 4), pb[it]);
        }
    };
    // ---- compute from smem stage s ----
    auto compute = [&](int s) {
        const uint32_t Ab = sb + s * STAGE_BYTES;
        const uint32_t Bb = Ab + 16384;
#pragma unroll
        for (int kc = 0; kc < 2; kc++) {
            uint32_t ah[2][4], al[2][4];
#pragma unroll
            for (int mt = 0; mt < 2; mt++) {
                const uint32_t ra = Ab + aRow[mt] * 128;
                const int sw = aRow[mt] & 7;
                ldsm4(ah[mt], ra + (((kc * 2 + kh    ) ^ sw) << 4));
                ldsm4(al[mt], ra + (((kc * 2 + kh + 4) ^ sw) << 4));
            }
#pragma unroll
            for (int g = 0; g < 4; g++) {
                const uint32_t rb = Bb + bN[g] * 128;
                const int sw = bN[g] & 7;
                uint32_t bh[4], bl[4];
                ldsm4(bh, rb + (((kc * 2 + mh    ) ^ sw) << 4));
                ldsm4(bl, rb + (((kc * 2 + mh + 4) ^ sw) << 4));
#pragma unroll
                for (int mt = 0; mt < 2; mt++) {
                    mma16816(acc[mt][2 * g],     ah[mt], bh);
                    mma16816(acc[mt][2 * g + 1], ah[mt], bh + 2);
                    mma16816(acc[mt][2 * g],     ah[mt], bl);
                    mma16816(acc[mt][2 * g + 1], ah[mt], bl + 2);
                    mma16816(acc[mt][2 * g],     al[mt], bh);
                    mma16816(acc[mt][2 * g + 1], al[mt], bh + 2);
                }
            }
        }
    };

    // ---- pipelined mainloop ----
    gload(0);
    swrite(0);
    __syncthreads();
    for (int kb = 0; kb < nkb; kb++) {
        const int s = kb & 1;
        if (kb + 1 < nkb) gload(kb + 1);
        compute(s);
        __syncthreads();
        if (kb + 1 < nkb) {
            swrite(s ^ 1);
            __syncthreads();
        }
    }

    // ---- epilogue: bias (+ReLU), write fp32 ----
    const int qr = lane >> 2;
    const int qc = (lane & 3) * 2;
#pragma unroll
    for (int mt = 0; mt < 2; mt++) {
#pragma unroll
        for (int nt = 0; nt < 8; nt++) {
            const int r = row0 + wm0 + mt * 16 + qr;
            const int c = col0 + wn0 + nt * 8 + qc;
            const float b0 = bias[c], b1 = bias[c + 1];
            float v0 = acc[mt][nt][0] + b0;
            float v1 = acc[mt][nt][1] + b1;
            float v2 = acc[mt][nt][2] + b0;
            float v3 = acc[mt][nt][3] + b1;
            if (relu) {
                v0 = fmaxf(v0, 0.f); v1 = fmaxf(v1, 0.f);
                v2 = fmaxf(v2, 0.f); v3 = fmaxf(v3, 0.f);
            }
            float2 w0 = make_float2(v0, v1);
            float2 w1 = make_float2(v2, v3);
            *(float2*)(C + (size_t)r * N + c) = w0;
            *(float2*)(C + (size_t)(r + 8) * N + c) = w1;
        }
    }
}

// ---------------------------------------------------------------------------
// Flash-attention (fp32, non-causal) — unchanged
// ---------------------------------------------------------------------------
__global__ __launch_bounds__(256) void attn_kernel(
    const float* __restrict__ q, const float* __restrict__ k,
    const float* __restrict__ v, float* __restrict__ o, int L)
{
    __shared__ float Qt[64][64];
    __shared__ float KP[64][64];
    __shared__ float Vs[64][64];

    const int bh = blockIdx.y;
    const int b  = bh / HEADS;
    const int h  = bh % HEADS;
    const int l0 = blockIdx.x * 64;
    const int tid = threadIdx.x;
    const int tr = tid >> 4, tc = tid & 15;
    const int r0 = tr * 4, c0 = tc * 4;

    const size_t base = ((size_t)b * L) * D_MODEL + h * HEAD_DIM;

    for (int i = tid; i < 64 * 16; i += 256) {
        int rr = i >> 4;
        int cc = (i & 15) * 4;
        float4 qv = *(const float4*)(q + base + (size_t)(l0 + rr) * D_MODEL + cc);
        Qt[cc + 0][rr] = qv.x; Qt[cc + 1][rr] = qv.y;
        Qt[cc + 2][rr] = qv.z; Qt[cc + 3][rr] = qv.w;
    }

    float m_i[4], l_i[4], acc[4][4];
#pragma unroll
    for (int i = 0; i < 4; i++) {
        m_i[i] = -3.0e38f; l_i[i] = 0.f;
#pragma unroll
        for (int j = 0; j < 4; j++) acc[i][j] = 0.f;
    }

    for (int s0 = 0; s0 < L; s0 += 64) {
        __syncthreads();
        for (int i = tid; i < 64 * 16; i += 256) {
            int rr = i >> 4;
            int cc = (i & 15) * 4;
            float4 kv = *(const float4*)(k + base + (size_t)(s0 + rr) * D_MODEL + cc);
            KP[cc + 0][rr] = kv.x; KP[cc + 1][rr] = kv.y;
            KP[cc + 2][rr] = kv.z; KP[cc + 3][rr] = kv.w;
            float4 vv = *(const float4*)(v + base + (size_t)(s0 + rr) * D_MODEL + cc);
            *(float4*)&Vs[rr][cc] = vv;
        }
        __syncthreads();

        float s[4][4];
#pragma unroll
        for (int i = 0; i < 4; i++)
#pragma unroll
            for (int j = 0; j < 4; j++) s[i][j] = 0.f;
        for (int kk = 0; kk < 64; kk++) {
            float4 qv = *(const float4*)&Qt[kk][r0];
            float4 kv = *(const float4*)&KP[kk][c0];
            float qa[4] = {qv.x, qv.y, qv.z, qv.w};
            float ka[4] = {kv.x, kv.y, kv.z, kv.w};
#pragma unroll
            for (int i = 0; i < 4; i++)
#pragma unroll
                for (int j = 0; j < 4; j++)
                    s[i][j] = fmaf(qa[i], ka[j], s[i][j]);
        }

        float p[4][4];
#pragma unroll
        for (int i = 0; i < 4; i++) {
            float tmax = -3.0e38f;
#pragma unroll
            for (int j = 0; j < 4; j++) {
                s[i][j] *= 0.125f;
                tmax = fmaxf(tmax, s[i][j]);
            }
#pragma unroll
            for (int off = 1; off < 16; off <<= 1)
                tmax = fmaxf(tmax, __shfl_xor_sync(0xffffffffu, tmax, off));
            float mnew = fmaxf(m_i[i], tmax);
            float corr = __expf(m_i[i] - mnew);
            l_i[i] *= corr;
#pragma unroll
            for (int j = 0; j < 4; j++) acc[i][j] *= corr;
            float rs = 0.f;
#pragma unroll
            for (int j = 0; j < 4; j++) {
                p[i][j] = __expf(s[i][j] - mnew);
                rs += p[i][j];
            }
#pragma unroll
            for (int off = 1; off < 16; off <<= 1)
                rs += __shfl_xor_sync(0xffffffffu, rs, off);
            l_i[i] += rs;
            m_i[i] = mnew;
        }

        __syncthreads();
#pragma unroll
        for (int i = 0; i < 4; i++)
#pragma unroll
            for (int j = 0; j < 4; j++)
                KP[c0 + j][r0 + i] = p[i][j];
        __syncthreads();

        for (int ss = 0; ss < 64; ss++) {
            float4 pv = *(const float4*)&KP[ss][r0];
            float4 vv = *(const float4*)&Vs[ss][c0];
            float pa[4] = {pv.x, pv.y, pv.z, pv.w};
            float va[4] = {vv.x, vv.y, vv.z, vv.w};
#pragma unroll
            for (int i = 0; i < 4; i++)
#pragma unroll
                for (int j = 0; j < 4; j++)
                    acc[i][j] = fmaf(pa[i], va[j], acc[i][j]);
        }
    }

#pragma unroll
    for (int i = 0; i < 4; i++) {
        float inv = 1.f / l_i[i];
#pragma unroll
        for (int j = 0; j < 4; j++)
            o[base + (size_t)(l0 + r0 + i) * D_MODEL + c0 + j] = acc[i][j] * inv;
    }
}

// ---------------------------------------------------------------------------
// Fused residual + LayerNorm — unchanged
// ---------------------------------------------------------------------------
__global__ __launch_bounds__(256) void ln_residual_kernel(
    const float* __restrict__ a, const float* __restrict__ r,
    const float* __restrict__ g, const float* __restrict__ beta,
    float* __restrict__ out)
{
    __shared__ float red[8];
    const int row = blockIdx.x;
    const int tid = threadIdx.x;
    const int lane = tid & 31, warp = tid >> 5;
    const size_t off = (size_t)row * D_MODEL + tid * 4;

    float4 va = *(const float4*)(a + off);
    float4 vr = *(const float4*)(r + off);
    float x[4] = {va.x + vr.x, va.y + vr.y, va.z + vr.z, va.w + vr.w};

    float sum = x[0] + x[1] + x[2] + x[3];
#pragma unroll
    for (int o = 16; o; o >>= 1) sum += __shfl_down_sync(0xffffffffu, sum, o);
    if (lane == 0) red[warp] = sum;
    __syncthreads();
    if (warp == 0) {
        float v = (lane < 8) ? red[lane] : 0.f;
#pragma unroll
        for (int o = 4; o; o >>= 1) v += __shfl_down_sync(0xffu, v, o);
        if (lane == 0) red[0] = v;
    }
    __syncthreads();
    const float mu = red[0] * (1.f / D_MODEL);
    __syncthreads();

    float sq = 0.f;
#pragma unroll
    for (int i = 0; i < 4; i++) {
        float d = x[i] - mu;
        sq += d * d;
    }
#pragma unroll
    for (int o = 16; o; o >>= 1) sq += __shfl_down_sync(0xffffffffu, sq, o);
    if (lane == 0) red[warp] = sq;
    __syncthreads();
    if (warp == 0) {
        float v = (lane < 8) ? red[lane] : 0.f;
#pragma unroll
        for (int o = 4; o; o >>= 1) v += __shfl_down_sync(0xffu, v, o);
        if (lane == 0) red[0] = v;
    }
    __syncthreads();
    const float rstd = rsqrtf(red[0] * (1.f / D_MODEL) + EPS);

    float4 gg = *(const float4*)(g + tid * 4);
    float4 bb = *(const float4*)(beta + tid * 4);
    float ga[4] = {gg.x, gg.y, gg.z, gg.w};
    float ba[4] = {bb.x, bb.y, bb.z, bb.w};
    float y[4];
#pragma unroll
    for (int i = 0; i < 4; i++)
        y[i] = (x[i] - mu) * rstd * ga[i] + ba[i];
    *(float4*)(out + off) = *(float4*)&y[0];
}

// ---------------------------------------------------------------------------
// Launch sequence
// ---------------------------------------------------------------------------
extern "C" void kernel_launch(void* const* d_in, const int* in_sizes, int n_in,
                              void* d_out, int out_size)
{
    const float* x  = (const float*)d_in[0];
    const float* Wq = (const float*)d_in[1];
    const float* bq = (const float*)d_in[2];
    const float* Wk = (const float*)d_in[3];
    const float* bk = (const float*)d_in[4];
    const float* Wv = (const float*)d_in[5];
    const float* bv = (const float*)d_in[6];
    const float* Wm = (const float*)d_in[7];
    const float* bm = (const float*)d_in[8];
    const float* W1 = (const float*)d_in[9];
    const float* b1 = (const float*)d_in[10];
    const float* W2 = (const float*)d_in[11];
    const float* b2 = (const float*)d_in[12];
    const float* g1  = (const float*)d_in[13];
    const float* be1 = (const float*)d_in[14];
    const float* g2  = (const float*)d_in[15];
    const float* be2 = (const float*)d_in[16];
    float* out = (float*)d_out;

    const int M = in_sizes[0] / D_MODEL;   // 4096
    const int L = SEQ_L;
    const int B = M / L;

    float *q, *k, *v, *attn, *proj, *h, *ff, *tmp;
    cudaGetSymbolAddress((void**)&q,    g_q);
    cudaGetSymbolAddress((void**)&k,    g_k);
    cudaGetSymbolAddress((void**)&v,    g_v);
    cudaGetSymbolAddress((void**)&attn, g_attn);
    cudaGetSymbolAddress((void**)&proj, g_proj);
    cudaGetSymbolAddress((void**)&h,    g_h);
    cudaGetSymbolAddress((void**)&ff,   g_ff);
    cudaGetSymbolAddress((void**)&tmp,  g_tmp);

    __nv_bfloat16 *wqh, *wql, *wkh, *wkl, *wvh, *wvl, *wmh, *wml, *w1h, *w1l, *w2h, *w2l;
    cudaGetSymbolAddress((void**)&wqh, g_wq_h); cudaGetSymbolAddress((void**)&wql, g_wq_l);
    cudaGetSymbolAddress((void**)&wkh, g_wk_h); cudaGetSymbolAddress((void**)&wkl, g_wk_l);
    cudaGetSymbolAddress((void**)&wvh, g_wv_h); cudaGetSymbolAddress((void**)&wvl, g_wv_l);
    cudaGetSymbolAddress((void**)&wmh, g_wm_h); cudaGetSymbolAddress((void**)&wml, g_wm_l);
    cudaGetSymbolAddress((void**)&w1h, g_w1_h); cudaGetSymbolAddress((void**)&w1l, g_w1_l);
    cudaGetSymbolAddress((void**)&w2h, g_w2_h); cudaGetSymbolAddress((void**)&w2l, g_w2_l);

    static bool attr_set = false;
    if (!attr_set) {
        cudaFuncSetAttribute(gemm_tc_kernel,
                             cudaFuncAttributeMaxDynamicSharedMemorySize, GEMM_SMEM_BYTES);
        attr_set = true;
    }

    dim3 blk(256);

    // weight prep: transpose + hi/lo split
    transpose_split_kernel<<<dim3(D_MODEL / 32, D_MODEL / 32), blk>>>(Wq, wqh, wql, D_MODEL, D_MODEL);
    transpose_split_kernel<<<dim3(D_MODEL / 32, D_MODEL / 32), blk>>>(Wk, wkh, wkl, D_MODEL, D_MODEL);
    transpose_split_kernel<<<dim3(D_MODEL / 32, D_MODEL / 32), blk>>>(Wv, wvh, wvl, D_MODEL, D_MODEL);
    transpose_split_kernel<<<dim3(D_MODEL / 32, D_MODEL / 32), blk>>>(Wm, wmh, wml, D_MODEL, D_MODEL);
    transpose_split_kernel<<<dim3(FF_DIM / 32, D_MODEL / 32), blk>>>(W1, w1h, w1l, D_MODEL, FF_DIM);
    transpose_split_kernel<<<dim3(D_MODEL / 32, FF_DIM / 32), blk>>>(W2, w2h, w2l, FF_DIM, D_MODEL);

    dim3 grid_d(D_MODEL / 128, M / 128);   // (8, 32)
    dim3 grid_f(FF_DIM / 128,  M / 128);   // (32, 32)

    // QKV projections
    gemm_tc_kernel<<<grid_d, blk, GEMM_SMEM_BYTES>>>(x, wqh, wql, bq, q, M, D_MODEL, D_MODEL, 0);
    gemm_tc_kernel<<<grid_d, blk, GEMM_SMEM_BYTES>>>(x, wkh, wkl, bk, k, M, D_MODEL, D_MODEL, 0);
    gemm_tc_kernel<<<grid_d, blk, GEMM_SMEM_BYTES>>>(x, wvh, wvl, bv, v, M, D_MODEL, D_MODEL, 0);

    // attention
    dim3 agrid(L / 64, B * HEADS);
    attn_kernel<<<agrid, blk>>>(q, k, v, attn, L);

    // output projection + residual LN
    gemm_tc_kernel<<<grid_d, blk, GEMM_SMEM_BYTES>>>(attn, wmh, wml, bm, proj, M, D_MODEL, D_MODEL, 0);
    ln_residual_kernel<<<M, blk>>>(x, proj, g1, be1, h);

    // FFN
    gemm_tc_kernel<<<grid_f, blk, GEMM_SMEM_BYTES>>>(h, w1h, w1l, b1, ff, M, FF_DIM, D_MODEL, 1);
    gemm_tc_kernel<<<grid_d, blk, GEMM_SMEM_BYTES>>>(ff, w2h, w2l, b2, tmp, M, D_MODEL, FF_DIM, 0);
    ln_residual_kernel<<<M, blk>>>(h, tmp, g2, be2, out);
}

// round 5
// speedup vs baseline: 2.6239x; 1.6295x over previous
#include <cuda_runtime.h>
#include <cuda_bf16.h>
#include <math.h>
#include <stdint.h>

// ---------------------------------------------------------------------------
// Fixed problem shape
// ---------------------------------------------------------------------------
#define D_MODEL 1024
#define HEADS   16
#define HEAD_DIM 64
#define FF_DIM  4096
#define SEQ_L   2048
#define EPS     1e-5f
#define MROWS   4096      // B * L

// ---------------------------------------------------------------------------
// Scratch (static device globals; no runtime allocation allowed)
// ---------------------------------------------------------------------------
__device__ float g_proj[MROWS * D_MODEL];
__device__ float g_h   [MROWS * D_MODEL];
__device__ float g_tmp [MROWS * D_MODEL];

// split activations (bf16 hi/lo)
__device__ __nv_bfloat16 g_xh[MROWS * D_MODEL];
__device__ __nv_bfloat16 g_xl[MROWS * D_MODEL];
__device__ __nv_bfloat16 g_qh[MROWS * D_MODEL];
__device__ __nv_bfloat16 g_ql[MROWS * D_MODEL];
__device__ __nv_bfloat16 g_kh[MROWS * D_MODEL];
__device__ __nv_bfloat16 g_kl[MROWS * D_MODEL];
__device__ __nv_bfloat16 g_vh[MROWS * D_MODEL];
__device__ __nv_bfloat16 g_vl[MROWS * D_MODEL];
__device__ __nv_bfloat16 g_ah[MROWS * D_MODEL];
__device__ __nv_bfloat16 g_al[MROWS * D_MODEL];
__device__ __nv_bfloat16 g_hh[MROWS * D_MODEL];
__device__ __nv_bfloat16 g_hl[MROWS * D_MODEL];
__device__ __nv_bfloat16 g_ffh[MROWS * FF_DIM];
__device__ __nv_bfloat16 g_ffl[MROWS * FF_DIM];

// weight transposed+split scratch: [N][K] bf16 hi / lo
__device__ __nv_bfloat16 g_wq_h[D_MODEL * D_MODEL];
__device__ __nv_bfloat16 g_wq_l[D_MODEL * D_MODEL];
__device__ __nv_bfloat16 g_wk_h[D_MODEL * D_MODEL];
__device__ __nv_bfloat16 g_wk_l[D_MODEL * D_MODEL];
__device__ __nv_bfloat16 g_wv_h[D_MODEL * D_MODEL];
__device__ __nv_bfloat16 g_wv_l[D_MODEL * D_MODEL];
__device__ __nv_bfloat16 g_wm_h[D_MODEL * D_MODEL];
__device__ __nv_bfloat16 g_wm_l[D_MODEL * D_MODEL];
__device__ __nv_bfloat16 g_w1_h[D_MODEL * FF_DIM];
__device__ __nv_bfloat16 g_w1_l[D_MODEL * FF_DIM];
__device__ __nv_bfloat16 g_w2_h[FF_DIM * D_MODEL];
__device__ __nv_bfloat16 g_w2_l[FF_DIM * D_MODEL];

// ---------------------------------------------------------------------------
// Helpers (base sm_100-safe: ldmatrix + mma.sync only)
// ---------------------------------------------------------------------------
__device__ __forceinline__ uint32_t smem_u32(const void* p) {
    uint32_t a;
    asm("{ .reg .u64 t; cvta.to.shared.u64 t, %1; cvt.u32.u64 %0, t; }" : "=r"(a) : "l"(p));
    return a;
}
__device__ __forceinline__ void ldsm4(uint32_t* r, uint32_t addr) {
    asm volatile("ldmatrix.sync.aligned.m8n8.x4.shared.b16 {%0,%1,%2,%3}, [%4];"
                 : "=r"(r[0]), "=r"(r[1]), "=r"(r[2]), "=r"(r[3]) : "r"(addr));
}
__device__ __forceinline__ void ldsm4t(uint32_t* r, uint32_t addr) {
    asm volatile("ldmatrix.sync.aligned.m8n8.x4.trans.shared.b16 {%0,%1,%2,%3}, [%4];"
                 : "=r"(r[0]), "=r"(r[1]), "=r"(r[2]), "=r"(r[3]) : "r"(addr));
}
__device__ __forceinline__ void mma16816(float* d, const uint32_t* a, const uint32_t* b) {
    asm volatile("mma.sync.aligned.m16n8k16.row.col.f32.bf16.bf16.f32 "
                 "{%0,%1,%2,%3}, {%4,%5,%6,%7}, {%8,%9}, {%0,%1,%2,%3};"
                 : "+f"(d[0]), "+f"(d[1]), "+f"(d[2]), "+f"(d[3])
                 : "r"(a[0]), "r"(a[1]), "r"(a[2]), "r"(a[3]), "r"(b[0]), "r"(b[1]));
}
__device__ __forceinline__ void sts_v4(uint32_t addr, uint4 v) {
    asm volatile("st.shared.v4.b32 [%0], {%1, %2, %3, %4};"
                 :: "r"(addr), "r"(v.x), "r"(v.y), "r"(v.z), "r"(v.w) : "memory");
}
__device__ __forceinline__ uint32_t packbf(float a, float b) {
    __nv_bfloat162 t = __float22bfloat162_rn(make_float2(a, b));
    return *reinterpret_cast<uint32_t*>(&t);
}
__device__ __forceinline__ float2 unpackbf(uint32_t u) {
    return __bfloat1622float2(*reinterpret_cast<__nv_bfloat162*>(&u));
}

// ---------------------------------------------------------------------------
// Weight transpose + hi/lo bf16 split: W[K,N] fp32 -> Th/Tl[N,K] bf16
// ---------------------------------------------------------------------------
__global__ __launch_bounds__(256) void transpose_split_kernel(
    const float* __restrict__ W, __nv_bfloat16* __restrict__ Th,
    __nv_bfloat16* __restrict__ Tl, int K, int N)
{
    __shared__ float t[32][33];
    const int n0 = blockIdx.x * 32, k0 = blockIdx.y * 32;
    const int tx = threadIdx.x & 31, ty = threadIdx.x >> 5;
#pragma unroll
    for (int i = 0; i < 4; i++)
        t[ty + i * 8][tx] = W[(size_t)(k0 + ty + i * 8) * N + n0 + tx];
    __syncthreads();
#pragma unroll
    for (int i = 0; i < 4; i++) {
        float v = t[tx][ty + i * 8];
        __nv_bfloat16 h = __float2bfloat16(v);
        __nv_bfloat16 l = __float2bfloat16(v - __bfloat162float(h));
        size_t o = (size_t)(n0 + ty + i * 8) * K + k0 + tx;
        Th[o] = h;
        Tl[o] = l;
    }
}

// ---------------------------------------------------------------------------
// Elementwise hi/lo split: x fp32 -> xh, xl bf16
// ---------------------------------------------------------------------------
__global__ __launch_bounds__(256) void split_kernel(
    const float* __restrict__ x, __nv_bfloat16* __restrict__ xh,
    __nv_bfloat16* __restrict__ xl, int n4)
{
    int i = blockIdx.x * 256 + threadIdx.x;
    if (i >= n4) return;
    float4 v = *(const float4*)(x + (size_t)i * 4);
    uint32_t h0 = packbf(v.x, v.y), h1 = packbf(v.z, v.w);
    float2 f0 = unpackbf(h0), f1 = unpackbf(h1);
    uint32_t l0 = packbf(v.x - f0.x, v.y - f0.y);
    uint32_t l1 = packbf(v.z - f1.x, v.w - f1.y);
    *(uint2*)((char*)xh + (size_t)i * 8) = make_uint2(h0, h1);
    *(uint2*)((char*)xl + (size_t)i * 8) = make_uint2(l0, l1);
}

// ---------------------------------------------------------------------------
// HMMA GEMM: C = A(split bf16) @ BT(split bf16)^T + bias, opt ReLU.
// Outputs: fp32 Cf (if non-null) and/or split bf16 Ch/Cl (if non-null).
// 128x128 CTA tile, BK=32, 256 threads (4Mx2N warps, 32x64 warp tile).
// SMEM rows = 128B = [hi 64B | lo 64B], XOR swizzle, double buffered.
// ---------------------------------------------------------------------------
#define TBK 32
#define STAGE_BYTES 32768
#define GEMM_SMEM_BYTES (2 * STAGE_BYTES)

__global__ __launch_bounds__(256, 1)
void gemm_tc_kernel(const __nv_bfloat16* __restrict__ Ah,
                    const __nv_bfloat16* __restrict__ Al,
                    const __nv_bfloat16* __restrict__ BTh,
                    const __nv_bfloat16* __restrict__ BTl,
                    const float* __restrict__ bias,
                    float* __restrict__ Cf,
                    __nv_bfloat16* __restrict__ Ch,
                    __nv_bfloat16* __restrict__ Cl,
                    int M, int N, int K, int relu)
{
    extern __shared__ char smem[];
    const uint32_t sb = smem_u32(smem);

    const int tid = threadIdx.x;
    const int wid = tid >> 5;
    const int lane = tid & 31;
    const int row0 = blockIdx.y * 128;
    const int col0 = blockIdx.x * 128;
    const int wm0 = (wid & 3) * 32;
    const int wn0 = (wid >> 2) * 64;
    const int nkb = K / TBK;

    // staging coords: each thread copies 4 A-chunks + 4 B-chunks (16B) per stage
    const int sr = tid >> 3;              // base row 0..31 (+ it*32)
    const int sj = tid & 7;               // chunk 0..7 (0-3 hi, 4-7 lo)
    const __nv_bfloat16* Asrc = (sj < 4) ? Ah : Al;
    const __nv_bfloat16* Bsrc = (sj < 4) ? BTh : BTl;
    const int sk = (sj & 3) * 8;

    // compute-lane coords
    const int lr = lane & 7;
    const int mh = (lane >> 3) & 1;
    const int kh = (lane >> 4) & 1;
    uint32_t aRow[2], bN[4];
#pragma unroll
    for (int mt = 0; mt < 2; mt++) aRow[mt] = wm0 + mt * 16 + mh * 8 + lr;
#pragma unroll
    for (int g = 0; g < 4; g++)    bN[g]   = wn0 + g * 16 + kh * 8 + lr;

    float acc[2][8][4];
#pragma unroll
    for (int mt = 0; mt < 2; mt++)
#pragma unroll
        for (int nt = 0; nt < 8; nt++)
#pragma unroll
            for (int i = 0; i < 4; i++) acc[mt][nt][i] = 0.f;

    uint4 pa[4], pb[4];
    auto gload = [&](int kb) {
#pragma unroll
        for (int it = 0; it < 4; it++) {
            pa[it] = *(const uint4*)(Asrc + (size_t)(row0 + sr + it * 32) * K + kb * TBK + sk);
            pb[it] = *(const uint4*)(Bsrc + (size_t)(col0 + sr + it * 32) * K + kb * TBK + sk);
        }
    };
    auto swrite = [&](int s) {
        const uint32_t Ab = sb + s * STAGE_BYTES;
        const uint32_t Bb = Ab + 16384;
#pragma unroll
        for (int it = 0; it < 4; it++) {
            const int r = sr + it * 32;
            const uint32_t off = r * 128 + ((sj ^ (r & 7)) << 4);
            sts_v4(Ab + off, pa[it]);
            sts_v4(Bb + off, pb[it]);
        }
    };
    auto compute = [&](int s) {
        const uint32_t Ab = sb + s * STAGE_BYTES;
        const uint32_t Bb = Ab + 16384;
#pragma unroll
        for (int kc = 0; kc < 2; kc++) {
            uint32_t ah[2][4], al[2][4];
#pragma unroll
            for (int mt = 0; mt < 2; mt++) {
                const uint32_t ra = Ab + aRow[mt] * 128;
                const int sw = aRow[mt] & 7;
                ldsm4(ah[mt], ra + (((kc * 2 + kh    ) ^ sw) << 4));
                ldsm4(al[mt], ra + (((kc * 2 + kh + 4) ^ sw) << 4));
            }
#pragma unroll
            for (int g = 0; g < 4; g++) {
                const uint32_t rb = Bb + bN[g] * 128;
                const int sw = bN[g] & 7;
                uint32_t bh[4], bl[4];
                ldsm4(bh, rb + (((kc * 2 + mh    ) ^ sw) << 4));
                ldsm4(bl, rb + (((kc * 2 + mh + 4) ^ sw) << 4));
#pragma unroll
                for (int mt = 0; mt < 2; mt++) {
                    mma16816(acc[mt][2 * g],     ah[mt], bh);
                    mma16816(acc[mt][2 * g + 1], ah[mt], bh + 2);
                    mma16816(acc[mt][2 * g],     ah[mt], bl);
                    mma16816(acc[mt][2 * g + 1], ah[mt], bl + 2);
                    mma16816(acc[mt][2 * g],     al[mt], bh);
                    mma16816(acc[mt][2 * g + 1], al[mt], bh + 2);
                }
            }
        }
    };

    gload(0);
    swrite(0);
    __syncthreads();
    for (int kb = 0; kb < nkb; kb++) {
        const int s = kb & 1;
        if (kb + 1 < nkb) gload(kb + 1);
        compute(s);
        __syncthreads();
        if (kb + 1 < nkb) {
            swrite(s ^ 1);
            __syncthreads();
        }
    }

    // epilogue
    const int qr = lane >> 2;
    const int qc = (lane & 3) * 2;
#pragma unroll
    for (int mt = 0; mt < 2; mt++) {
#pragma unroll
        for (int nt = 0; nt < 8; nt++) {
            const int r = row0 + wm0 + mt * 16 + qr;
            const int c = col0 + wn0 + nt * 8 + qc;
            const float b0 = bias[c], b1 = bias[c + 1];
            float v0 = acc[mt][nt][0] + b0;
            float v1 = acc[mt][nt][1] + b1;
            float v2 = acc[mt][nt][2] + b0;
            float v3 = acc[mt][nt][3] + b1;
            if (relu) {
                v0 = fmaxf(v0, 0.f); v1 = fmaxf(v1, 0.f);
                v2 = fmaxf(v2, 0.f); v3 = fmaxf(v3, 0.f);
            }
            if (Cf) {
                *(float2*)(Cf + (size_t)r * N + c) = make_float2(v0, v1);
                *(float2*)(Cf + (size_t)(r + 8) * N + c) = make_float2(v2, v3);
            }
            if (Ch) {
                uint32_t h0 = packbf(v0, v1);
                uint32_t h1 = packbf(v2, v3);
                float2 f0 = unpackbf(h0), f1 = unpackbf(h1);
                uint32_t l0 = packbf(v0 - f0.x, v1 - f0.y);
                uint32_t l1 = packbf(v2 - f1.x, v3 - f1.y);
                *(uint32_t*)((char*)Ch + ((size_t)r * N + c) * 2) = h0;
                *(uint32_t*)((char*)Ch + ((size_t)(r + 8) * N + c) * 2) = h1;
                *(uint32_t*)((char*)Cl + ((size_t)r * N + c) * 2) = l0;
                *(uint32_t*)((char*)Cl + ((size_t)(r + 8) * N + c) * 2) = l1;
            }
        }
    }
}

// ---------------------------------------------------------------------------
// Flash-attention with HMMA (split-3 bf16, fp32 accum).
// CTA: (b, h, 128 q rows). 8 warps x 16 rows. 64-key blocks, double buffered.
// smem: Q 32KB (2 d-chunks, [hi|lo] rows) + K 2x16KB + V 2x16KB = 96KB.
// ---------------------------------------------------------------------------
#define ATTN_SMEM 98304

__global__ __launch_bounds__(256, 1)
void attn_tc_kernel(const __nv_bfloat16* __restrict__ qh, const __nv_bfloat16* __restrict__ ql,
                    const __nv_bfloat16* __restrict__ kh_g, const __nv_bfloat16* __restrict__ kl_g,
                    const __nv_bfloat16* __restrict__ vh_g, const __nv_bfloat16* __restrict__ vl_g,
                    __nv_bfloat16* __restrict__ oh, __nv_bfloat16* __restrict__ ol, int L)
{
    extern __shared__ char smem[];
    const uint32_t sb = smem_u32(smem);
    const uint32_t qoff = sb;
    const uint32_t koff = sb + 32768;
    const uint32_t voff = sb + 65536;

    const int tid = threadIdx.x;
    const int wid = tid >> 5;
    const int lane = tid & 31;
    const int bh = blockIdx.y;
    const int b = bh / HEADS;
    const int hd = (bh % HEADS) * HEAD_DIM;
    const int l0 = blockIdx.x * 128;
    const int tok0 = b * L + l0;      // first query token
    const int kbase = b * L;          // key token base

    const int lr = lane & 7;
    const int mh = (lane >> 3) & 1;
    const int khb = (lane >> 4) & 1;

    // ---- load Q tile into smem (2 d-chunks, [hi32|lo32] 128B rows) ----
#pragma unroll
    for (int it = 0; it < 8; it++) {
        int id = it * 256 + tid;                    // 0..2047
        int c = id >> 10, rem = id & 1023;
        int row = rem >> 3, j = rem & 7;
        const __nv_bfloat16* src = (j < 4) ? qh : ql;
        uint4 v = *(const uint4*)(src + (size_t)(tok0 + row) * D_MODEL + hd + c * 32 + (j & 3) * 8);
        sts_v4(qoff + c * 16384 + row * 128 + ((j ^ (row & 7)) << 4), v);
    }

    // ---- K/V staging ----
    uint4 rk[4], rv[4];
    auto gloadKV = [&](int kb) {
        const int t0 = kbase + kb * 64;
#pragma unroll
        for (int it = 0; it < 4; it++) {
            int id = it * 256 + tid;                // 0..1023
            {   // K: c = id>>9, row = (id>>3)&63, j = id&7
                int c = id >> 9, row = (id >> 3) & 63, j = id & 7;
                const __nv_bfloat16* src = (j < 4) ? kh_g : kl_g;
                rk[it] = *(const uint4*)(src + (size_t)(t0 + row) * D_MODEL + hd + c * 32 + (j & 3) * 8);
            }
            {   // V: half = id>=512, row = (id>>3)&63, j = id&7 (full 64-d rows)
                int row = (id >> 3) & 63, j = id & 7;
                const __nv_bfloat16* src = (id < 512) ? vh_g : vl_g;
                rv[it] = *(const uint4*)(src + (size_t)(t0 + row) * D_MODEL + hd + j * 8);
            }
        }
    };
    auto swriteKV = [&](int s) {
        const uint32_t kb_ = koff + s * 16384;
        const uint32_t vb_ = voff + s * 16384;
#pragma unroll
        for (int it = 0; it < 4; it++) {
            int id = it * 256 + tid;
            {
                int c = id >> 9, row = (id >> 3) & 63, j = id & 7;
                sts_v4(kb_ + c * 8192 + row * 128 + ((j ^ (row & 7)) << 4), rk[it]);
            }
            {
                int row = (id >> 3) & 63, j = id & 7;
                sts_v4(vb_ + ((id < 512) ? 0 : 8192) + row * 128 + ((j ^ (row & 7)) << 4), rv[it]);
            }
        }
    };

    // ---- preload Q fragments into registers (4 k16 steps, hi+lo) ----
    gloadKV(0);
    swriteKV(0);
    __syncthreads();

    uint32_t qah[4][4], qal[4][4];
    {
        const int aRow = wid * 16 + mh * 8 + lr;
        const int sw = aRow & 7;
#pragma unroll
        for (int c = 0; c < 2; c++) {
#pragma unroll
            for (int kc = 0; kc < 2; kc++) {
                const int t = c * 2 + kc;
                const uint32_t base = qoff + c * 16384 + aRow * 128;
                ldsm4(qah[t], base + (((kc * 2 + khb    ) ^ sw) << 4));
                ldsm4(qal[t], base + (((kc * 2 + khb + 4) ^ sw) << 4));
            }
        }
    }

    float m0 = -3.0e38f, m1 = -3.0e38f, li0 = 0.f, li1 = 0.f;
    float oacc[8][4];
#pragma unroll
    for (int j = 0; j < 8; j++)
#pragma unroll
        for (int i = 0; i < 4; i++) oacc[j][i] = 0.f;

    const int nkb = L / 64;
    for (int kb = 0; kb < nkb; kb++) {
        const int s = kb & 1;
        if (kb + 1 < nkb) gloadKV(kb + 1);

        // ---- S = Q @ K^T (split-3) ----
        float sacc[8][4];
#pragma unroll
        for (int j = 0; j < 8; j++)
#pragma unroll
            for (int i = 0; i < 4; i++) sacc[j][i] = 0.f;

        const uint32_t kst = koff + s * 16384;
#pragma unroll
        for (int g = 0; g < 4; g++) {
            const int bN = g * 16 + khb * 8 + lr;
            const int sw = bN & 7;
#pragma unroll
            for (int c = 0; c < 2; c++) {
                const uint32_t rb = kst + c * 8192 + bN * 128;
#pragma unroll
                for (int kc = 0; kc < 2; kc++) {
                    const int t = c * 2 + kc;
                    uint32_t bh4[4], bl4[4];
                    ldsm4(bh4, rb + (((kc * 2 + mh    ) ^ sw) << 4));
                    ldsm4(bl4, rb + (((kc * 2 + mh + 4) ^ sw) << 4));
                    mma16816(sacc[2 * g],     qah[t], bh4);
                    mma16816(sacc[2 * g + 1], qah[t], bh4 + 2);
                    mma16816(sacc[2 * g],     qah[t], bl4);
                    mma16816(sacc[2 * g + 1], qah[t], bl4 + 2);
                    mma16816(sacc[2 * g],     qal[t], bh4);
                    mma16816(sacc[2 * g + 1], qal[t], bh4 + 2);
                }
            }
        }

        // ---- online softmax on fragments (rows l/4 and l/4+8) ----
#pragma unroll
        for (int j = 0; j < 8; j++)
#pragma unroll
            for (int i = 0; i < 4; i++) sacc[j][i] *= 0.125f;

        float mx0 = -3.0e38f, mx1 = -3.0e38f;
#pragma unroll
        for (int j = 0; j < 8; j++) {
            mx0 = fmaxf(mx0, fmaxf(sacc[j][0], sacc[j][1]));
            mx1 = fmaxf(mx1, fmaxf(sacc[j][2], sacc[j][3]));
        }
        mx0 = fmaxf(mx0, __shfl_xor_sync(0xffffffffu, mx0, 1));
        mx0 = fmaxf(mx0, __shfl_xor_sync(0xffffffffu, mx0, 2));
        mx1 = fmaxf(mx1, __shfl_xor_sync(0xffffffffu, mx1, 1));
        mx1 = fmaxf(mx1, __shfl_xor_sync(0xffffffffu, mx1, 2));
        const float mn0 = fmaxf(m0, mx0);
        const float mn1 = fmaxf(m1, mx1);
        const float co0 = __expf(m0 - mn0);
        const float co1 = __expf(m1 - mn1);
        float rs0 = 0.f, rs1 = 0.f;
#pragma unroll
        for (int j = 0; j < 8; j++) {
            sacc[j][0] = __expf(sacc[j][0] - mn0);
            sacc[j][1] = __expf(sacc[j][1] - mn0);
            sacc[j][2] = __expf(sacc[j][2] - mn1);
            sacc[j][3] = __expf(sacc[j][3] - mn1);
            rs0 += sacc[j][0] + sacc[j][1];
            rs1 += sacc[j][2] + sacc[j][3];
        }
        rs0 += __shfl_xor_sync(0xffffffffu, rs0, 1);
        rs0 += __shfl_xor_sync(0xffffffffu, rs0, 2);
        rs1 += __shfl_xor_sync(0xffffffffu, rs1, 1);
        rs1 += __shfl_xor_sync(0xffffffffu, rs1, 2);
        li0 = li0 * co0 + rs0;
        li1 = li1 * co1 + rs1;
        m0 = mn0; m1 = mn1;
#pragma unroll
        for (int j = 0; j < 8; j++) {
            oacc[j][0] *= co0; oacc[j][1] *= co0;
            oacc[j][2] *= co1; oacc[j][3] *= co1;
        }

        // ---- O += P @ V (split-3; V via ldmatrix.trans) ----
        const uint32_t vst = voff + s * 16384;
#pragma unroll
        for (int t = 0; t < 4; t++) {
            const int j0 = 2 * t, j1 = 2 * t + 1;
            uint32_t ph[4], pl[4];
            ph[0] = packbf(sacc[j0][0], sacc[j0][1]);
            ph[1] = packbf(sacc[j0][2], sacc[j0][3]);
            ph[2] = packbf(sacc[j1][0], sacc[j1][1]);
            ph[3] = packbf(sacc[j1][2], sacc[j1][3]);
#pragma unroll
            for (int i = 0; i < 4; i++) {
                float2 f = unpackbf(ph[i]);
                const float* sp = (i < 2) ? sacc[j0] : sacc[j1];
                int o = (i & 1) * 2;
                pl[i] = packbf(sp[o] - f.x, sp[o + 1] - f.y);
            }
            const int vRow = t * 16 + mh * 8 + lr;
            const int sw = vRow & 7;
            const uint32_t vrb = vst + vRow * 128;
#pragma unroll
            for (int g = 0; g < 4; g++) {
                uint32_t vh4[4], vl4[4];
                ldsm4t(vh4, vrb + (((g * 2 + khb) ^ sw) << 4));
                ldsm4t(vl4, vrb + 8192 + (((g * 2 + khb) ^ sw) << 4));
                mma16816(oacc[2 * g],     ph, vh4);
                mma16816(oacc[2 * g + 1], ph, vh4 + 2);
                mma16816(oacc[2 * g],     ph, vl4);
                mma16816(oacc[2 * g + 1], ph, vl4 + 2);
                mma16816(oacc[2 * g],     pl, vh4);
                mma16816(oacc[2 * g + 1], pl, vh4 + 2);
            }
        }

        __syncthreads();
        if (kb + 1 < nkb) {
            swriteKV(s ^ 1);
            __syncthreads();
        }
    }

    // ---- epilogue: normalize, split, write ----
    const float inv0 = 1.f / li0;
    const float inv1 = 1.f / li1;
    const int r0 = tok0 + wid * 16 + (lane >> 2);
    const int r1 = r0 + 8;
#pragma unroll
    for (int j = 0; j < 8; j++) {
        const int c = hd + j * 8 + (lane & 3) * 2;
        float v0 = oacc[j][0] * inv0, v1 = oacc[j][1] * inv0;
        float v2 = oacc[j][2] * inv1, v3 = oacc[j][3] * inv1;
        uint32_t h0 = packbf(v0, v1), h1 = packbf(v2, v3);
        float2 f0 = unpackbf(h0), f1 = unpackbf(h1);
        uint32_t lo0 = packbf(v0 - f0.x, v1 - f0.y);
        uint32_t lo1 = packbf(v2 - f1.x, v3 - f1.y);
        *(uint32_t*)((char*)oh + ((size_t)r0 * D_MODEL + c) * 2) = h0;
        *(uint32_t*)((char*)ol + ((size_t)r0 * D_MODEL + c) * 2) = lo0;
        *(uint32_t*)((char*)oh + ((size_t)r1 * D_MODEL + c) * 2) = h1;
        *(uint32_t*)((char*)ol + ((size_t)r1 * D_MODEL + c) * 2) = lo1;
    }
}

// ---------------------------------------------------------------------------
// Fused residual + LayerNorm (+ optional split bf16 outputs)
// ---------------------------------------------------------------------------
__global__ __launch_bounds__(256) void ln_residual_kernel(
    const float* __restrict__ a, const float* __restrict__ r,
    const float* __restrict__ g, const float* __restrict__ beta,
    float* __restrict__ out, __nv_bfloat16* __restrict__ outh,
    __nv_bfloat16* __restrict__ outl)
{
    __shared__ float red[8];
    const int row = blockIdx.x;
    const int tid = threadIdx.x;
    const int lane = tid & 31, warp = tid >> 5;
    const size_t off = (size_t)row * D_MODEL + tid * 4;

    float4 va = *(const float4*)(a + off);
    float4 vr = *(const float4*)(r + off);
    float x[4] = {va.x + vr.x, va.y + vr.y, va.z + vr.z, va.w + vr.w};

    float sum = x[0] + x[1] + x[2] + x[3];
#pragma unroll
    for (int o = 16; o; o >>= 1) sum += __shfl_down_sync(0xffffffffu, sum, o);
    if (lane == 0) red[warp] = sum;
    __syncthreads();
    if (warp == 0) {
        float v = (lane < 8) ? red[lane] : 0.f;
#pragma unroll
        for (int o = 4; o; o >>= 1) v += __shfl_down_sync(0xffu, v, o);
        if (lane == 0) red[0] = v;
    }
    __syncthreads();
    const float mu = red[0] * (1.f / D_MODEL);
    __syncthreads();

    float sq = 0.f;
#pragma unroll
    for (int i = 0; i < 4; i++) {
        float d = x[i] - mu;
        sq += d * d;
    }
#pragma unroll
    for (int o = 16; o; o >>= 1) sq += __shfl_down_sync(0xffffffffu, sq, o);
    if (lane == 0) red[warp] = sq;
    __syncthreads();
    if (warp == 0) {
        float v = (lane < 8) ? red[lane] : 0.f;
#pragma unroll
        for (int o = 4; o; o >>= 1) v += __shfl_down_sync(0xffu, v, o);
        if (lane == 0) red[0] = v;
    }
    __syncthreads();
    const float rstd = rsqrtf(red[0] * (1.f / D_MODEL) + EPS);

    float4 gg = *(const float4*)(g + tid * 4);
    float4 bb = *(const float4*)(beta + tid * 4);
    float y[4];
    y[0] = (x[0] - mu) * rstd * gg.x + bb.x;
    y[1] = (x[1] - mu) * rstd * gg.y + bb.y;
    y[2] = (x[2] - mu) * rstd * gg.z + bb.z;
    y[3] = (x[3] - mu) * rstd * gg.w + bb.w;
    *(float4*)(out + off) = *(float4*)&y[0];
    if (outh) {
        uint32_t h0 = packbf(y[0], y[1]), h1 = packbf(y[2], y[3]);
        float2 f0 = unpackbf(h0), f1 = unpackbf(h1);
        uint32_t l0 = packbf(y[0] - f0.x, y[1] - f0.y);
        uint32_t l1 = packbf(y[2] - f1.x, y[3] - f1.y);
        *(uint2*)((char*)outh + off * 2) = make_uint2(h0, h1);
        *(uint2*)((char*)outl + off * 2) = make_uint2(l0, l1);
    }
}

// ---------------------------------------------------------------------------
// Launch sequence
// ---------------------------------------------------------------------------
extern "C" void kernel_launch(void* const* d_in, const int* in_sizes, int n_in,
                              void* d_out, int out_size)
{
    const float* x  = (const float*)d_in[0];
    const float* Wq = (const float*)d_in[1];
    const float* bq = (const float*)d_in[2];
    const float* Wk = (const float*)d_in[3];
    const float* bk = (const float*)d_in[4];
    const float* Wv = (const float*)d_in[5];
    const float* bv = (const float*)d_in[6];
    const float* Wm = (const float*)d_in[7];
    const float* bm = (const float*)d_in[8];
    const float* W1 = (const float*)d_in[9];
    const float* b1 = (const float*)d_in[10];
    const float* W2 = (const float*)d_in[11];
    const float* b2 = (const float*)d_in[12];
    const float* g1  = (const float*)d_in[13];
    const float* be1 = (const float*)d_in[14];
    const float* g2  = (const float*)d_in[15];
    const float* be2 = (const float*)d_in[16];
    float* out = (float*)d_out;

    const int M = in_sizes[0] / D_MODEL;   // 4096
    const int L = SEQ_L;
    const int B = M / L;

    float *proj, *h, *tmp;
    cudaGetSymbolAddress((void**)&proj, g_proj);
    cudaGetSymbolAddress((void**)&h,    g_h);
    cudaGetSymbolAddress((void**)&tmp,  g_tmp);

    __nv_bfloat16 *xh, *xl, *qh, *ql, *kh, *kl, *vh, *vl, *ah, *al, *hh, *hl, *ffh, *ffl;
    cudaGetSymbolAddress((void**)&xh, g_xh); cudaGetSymbolAddress((void**)&xl, g_xl);
    cudaGetSymbolAddress((void**)&qh, g_qh); cudaGetSymbolAddress((void**)&ql, g_ql);
    cudaGetSymbolAddress((void**)&kh, g_kh); cudaGetSymbolAddress((void**)&kl, g_kl);
    cudaGetSymbolAddress((void**)&vh, g_vh); cudaGetSymbolAddress((void**)&vl, g_vl);
    cudaGetSymbolAddress((void**)&ah, g_ah); cudaGetSymbolAddress((void**)&al, g_al);
    cudaGetSymbolAddress((void**)&hh, g_hh); cudaGetSymbolAddress((void**)&hl, g_hl);
    cudaGetSymbolAddress((void**)&ffh, g_ffh); cudaGetSymbolAddress((void**)&ffl, g_ffl);

    __nv_bfloat16 *wqh, *wql, *wkh, *wkl, *wvh, *wvl, *wmh, *wml, *w1h, *w1l, *w2h, *w2l;
    cudaGetSymbolAddress((void**)&wqh, g_wq_h); cudaGetSymbolAddress((void**)&wql, g_wq_l);
    cudaGetSymbolAddress((void**)&wkh, g_wk_h); cudaGetSymbolAddress((void**)&wkl, g_wk_l);
    cudaGetSymbolAddress((void**)&wvh, g_wv_h); cudaGetSymbolAddress((void**)&wvl, g_wv_l);
    cudaGetSymbolAddress((void**)&wmh, g_wm_h); cudaGetSymbolAddress((void**)&wml, g_wm_l);
    cudaGetSymbolAddress((void**)&w1h, g_w1_h); cudaGetSymbolAddress((void**)&w1l, g_w1_l);
    cudaGetSymbolAddress((void**)&w2h, g_w2_h); cudaGetSymbolAddress((void**)&w2l, g_w2_l);

    static bool attr_set = false;
    if (!attr_set) {
        cudaFuncSetAttribute(gemm_tc_kernel,
                             cudaFuncAttributeMaxDynamicSharedMemorySize, GEMM_SMEM_BYTES);
        cudaFuncSetAttribute(attn_tc_kernel,
                             cudaFuncAttributeMaxDynamicSharedMemorySize, ATTN_SMEM);
        attr_set = true;
    }

    dim3 blk(256);

    // prep: weight transpose+split, x split
    transpose_split_kernel<<<dim3(D_MODEL / 32, D_MODEL / 32), blk>>>(Wq, wqh, wql, D_MODEL, D_MODEL);
    transpose_split_kernel<<<dim3(D_MODEL / 32, D_MODEL / 32), blk>>>(Wk, wkh, wkl, D_MODEL, D_MODEL);
    transpose_split_kernel<<<dim3(D_MODEL / 32, D_MODEL / 32), blk>>>(Wv, wvh, wvl, D_MODEL, D_MODEL);
    transpose_split_kernel<<<dim3(D_MODEL / 32, D_MODEL / 32), blk>>>(Wm, wmh, wml, D_MODEL, D_MODEL);
    transpose_split_kernel<<<dim3(FF_DIM / 32, D_MODEL / 32), blk>>>(W1, w1h, w1l, D_MODEL, FF_DIM);
    transpose_split_kernel<<<dim3(D_MODEL / 32, FF_DIM / 32), blk>>>(W2, w2h, w2l, FF_DIM, D_MODEL);
    split_kernel<<<(M * D_MODEL / 4 + 255) / 256, blk>>>(x, xh, xl, M * D_MODEL / 4);

    dim3 grid_d(D_MODEL / 128, M / 128);   // (8, 32)
    dim3 grid_f(FF_DIM / 128,  M / 128);   // (32, 32)

    // QKV projections -> split bf16 only
    gemm_tc_kernel<<<grid_d, blk, GEMM_SMEM_BYTES>>>(xh, xl, wqh, wql, bq, nullptr, qh, ql, M, D_MODEL, D_MODEL, 0);
    gemm_tc_kernel<<<grid_d, blk, GEMM_SMEM_BYTES>>>(xh, xl, wkh, wkl, bk, nullptr, kh, kl, M, D_MODEL, D_MODEL, 0);
    gemm_tc_kernel<<<grid_d, blk, GEMM_SMEM_BYTES>>>(xh, xl, wvh, wvl, bv, nullptr, vh, vl, M, D_MODEL, D_MODEL, 0);

    // attention (HMMA) -> split bf16
    dim3 agrid(L / 128, B * HEADS);        // (16, 32)
    attn_tc_kernel<<<agrid, blk, ATTN_SMEM>>>(qh, ql, kh, kl, vh, vl, ah, al, L);

    // output projection (fp32) + residual LN -> h fp32 + split
    gemm_tc_kernel<<<grid_d, blk, GEMM_SMEM_BYTES>>>(ah, al, wmh, wml, bm, proj, nullptr, nullptr, M, D_MODEL, D_MODEL, 0);
    ln_residual_kernel<<<M, blk>>>(x, proj, g1, be1, h, hh, hl);

    // FFN
    gemm_tc_kernel<<<grid_f, blk, GEMM_SMEM_BYTES>>>(hh, hl, w1h, w1l, b1, nullptr, ffh, ffl, M, FF_DIM, D_MODEL, 1);
    gemm_tc_kernel<<<grid_d, blk, GEMM_SMEM_BYTES>>>(ffh, ffl, w2h, w2l, b2, tmp, nullptr, nullptr, M, D_MODEL, FF_DIM, 0);
    ln_residual_kernel<<<M, blk>>>(h, tmp, g2, be2, out, nullptr, nullptr);
}

// round 6
// speedup vs baseline: 2.7410x; 1.0446x over previous
#include <cuda_runtime.h>
#include <cuda_bf16.h>
#include <math.h>
#include <stdint.h>

// ---------------------------------------------------------------------------
// Fixed problem shape
// ---------------------------------------------------------------------------
#define D_MODEL 1024
#define HEADS   16
#define HEAD_DIM 64
#define FF_DIM  4096
#define SEQ_L   2048
#define EPS     1e-5f
#define MROWS   4096      // B * L

// ---------------------------------------------------------------------------
// Scratch (static device globals; no runtime allocation allowed)
// ---------------------------------------------------------------------------
__device__ float g_proj[MROWS * D_MODEL];
__device__ float g_h   [MROWS * D_MODEL];
__device__ float g_tmp [MROWS * D_MODEL];

// split activations (bf16 hi/lo)
__device__ __nv_bfloat16 g_xh[MROWS * D_MODEL];
__device__ __nv_bfloat16 g_xl[MROWS * D_MODEL];
__device__ __nv_bfloat16 g_qh[MROWS * D_MODEL];
__device__ __nv_bfloat16 g_ql[MROWS * D_MODEL];
__device__ __nv_bfloat16 g_kh[MROWS * D_MODEL];
__device__ __nv_bfloat16 g_kl[MROWS * D_MODEL];
__device__ __nv_bfloat16 g_vh[MROWS * D_MODEL];
__device__ __nv_bfloat16 g_vl[MROWS * D_MODEL];
__device__ __nv_bfloat16 g_ah[MROWS * D_MODEL];
__device__ __nv_bfloat16 g_al[MROWS * D_MODEL];
__device__ __nv_bfloat16 g_hh[MROWS * D_MODEL];
__device__ __nv_bfloat16 g_hl[MROWS * D_MODEL];
__device__ __nv_bfloat16 g_ffh[MROWS * FF_DIM];
__device__ __nv_bfloat16 g_ffl[MROWS * FF_DIM];

// weight transposed+split scratch: [N][K] bf16 hi / lo
__device__ __nv_bfloat16 g_wq_h[D_MODEL * D_MODEL];
__device__ __nv_bfloat16 g_wq_l[D_MODEL * D_MODEL];
__device__ __nv_bfloat16 g_wk_h[D_MODEL * D_MODEL];
__device__ __nv_bfloat16 g_wk_l[D_MODEL * D_MODEL];
__device__ __nv_bfloat16 g_wv_h[D_MODEL * D_MODEL];
__device__ __nv_bfloat16 g_wv_l[D_MODEL * D_MODEL];
__device__ __nv_bfloat16 g_wm_h[D_MODEL * D_MODEL];
__device__ __nv_bfloat16 g_wm_l[D_MODEL * D_MODEL];
__device__ __nv_bfloat16 g_w1_h[D_MODEL * FF_DIM];
__device__ __nv_bfloat16 g_w1_l[D_MODEL * FF_DIM];
__device__ __nv_bfloat16 g_w2_h[FF_DIM * D_MODEL];
__device__ __nv_bfloat16 g_w2_l[FF_DIM * D_MODEL];

// ---------------------------------------------------------------------------
// Helpers (base sm_100-safe: ldmatrix + mma.sync + cp.async)
// ---------------------------------------------------------------------------
__device__ __forceinline__ uint32_t smem_u32(const void* p) {
    uint32_t a;
    asm("{ .reg .u64 t; cvta.to.shared.u64 t, %1; cvt.u32.u64 %0, t; }" : "=r"(a) : "l"(p));
    return a;
}
__device__ __forceinline__ void ldsm4(uint32_t* r, uint32_t addr) {
    asm volatile("ldmatrix.sync.aligned.m8n8.x4.shared.b16 {%0,%1,%2,%3}, [%4];"
                 : "=r"(r[0]), "=r"(r[1]), "=r"(r[2]), "=r"(r[3]) : "r"(addr));
}
__device__ __forceinline__ void ldsm4t(uint32_t* r, uint32_t addr) {
    asm volatile("ldmatrix.sync.aligned.m8n8.x4.trans.shared.b16 {%0,%1,%2,%3}, [%4];"
                 : "=r"(r[0]), "=r"(r[1]), "=r"(r[2]), "=r"(r[3]) : "r"(addr));
}
__device__ __forceinline__ void mma16816(float* d, const uint32_t* a, const uint32_t* b) {
    asm volatile("mma.sync.aligned.m16n8k16.row.col.f32.bf16.bf16.f32 "
                 "{%0,%1,%2,%3}, {%4,%5,%6,%7}, {%8,%9}, {%0,%1,%2,%3};"
                 : "+f"(d[0]), "+f"(d[1]), "+f"(d[2]), "+f"(d[3])
                 : "r"(a[0]), "r"(a[1]), "r"(a[2]), "r"(a[3]), "r"(b[0]), "r"(b[1]));
}
__device__ __forceinline__ void cp_async16(uint32_t saddr, const void* gptr) {
    asm volatile("cp.async.cg.shared.global [%0], [%1], 16;"
                 :: "r"(saddr), "l"(gptr) : "memory");
}
__device__ __forceinline__ void cp_commit() {
    asm volatile("cp.async.commit_group;" ::: "memory");
}
template<int N> __device__ __forceinline__ void cp_wait() {
    asm volatile("cp.async.wait_group %0;" :: "n"(N) : "memory");
}
__device__ __forceinline__ uint32_t packbf(float a, float b) {
    __nv_bfloat162 t = __float22bfloat162_rn(make_float2(a, b));
    return *reinterpret_cast<uint32_t*>(&t);
}
__device__ __forceinline__ float2 unpackbf(uint32_t u) {
    return __bfloat1622float2(*reinterpret_cast<__nv_bfloat162*>(&u));
}

// ---------------------------------------------------------------------------
// Weight transpose + hi/lo bf16 split: W[K,N] fp32 -> Th/Tl[N,K] bf16
// ---------------------------------------------------------------------------
__global__ __launch_bounds__(256) void transpose_split_kernel(
    const float* __restrict__ W, __nv_bfloat16* __restrict__ Th,
    __nv_bfloat16* __restrict__ Tl, int K, int N)
{
    __shared__ float t[32][33];
    const int n0 = blockIdx.x * 32, k0 = blockIdx.y * 32;
    const int tx = threadIdx.x & 31, ty = threadIdx.x >> 5;
#pragma unroll
    for (int i = 0; i < 4; i++)
        t[ty + i * 8][tx] = W[(size_t)(k0 + ty + i * 8) * N + n0 + tx];
    __syncthreads();
#pragma unroll
    for (int i = 0; i < 4; i++) {
        float v = t[tx][ty + i * 8];
        __nv_bfloat16 h = __float2bfloat16(v);
        __nv_bfloat16 l = __float2bfloat16(v - __bfloat162float(h));
        size_t o = (size_t)(n0 + ty + i * 8) * K + k0 + tx;
        Th[o] = h;
        Tl[o] = l;
    }
}

// ---------------------------------------------------------------------------
// Elementwise hi/lo split: x fp32 -> xh, xl bf16
// ---------------------------------------------------------------------------
__global__ __launch_bounds__(256) void split_kernel(
    const float* __restrict__ x, __nv_bfloat16* __restrict__ xh,
    __nv_bfloat16* __restrict__ xl, int n4)
{
    int i = blockIdx.x * 256 + threadIdx.x;
    if (i >= n4) return;
    float4 v = *(const float4*)(x + (size_t)i * 4);
    uint32_t h0 = packbf(v.x, v.y), h1 = packbf(v.z, v.w);
    float2 f0 = unpackbf(h0), f1 = unpackbf(h1);
    uint32_t l0 = packbf(v.x - f0.x, v.y - f0.y);
    uint32_t l1 = packbf(v.z - f1.x, v.w - f1.y);
    *(uint2*)((char*)xh + (size_t)i * 8) = make_uint2(h0, h1);
    *(uint2*)((char*)xl + (size_t)i * 8) = make_uint2(l0, l1);
}

// ---------------------------------------------------------------------------
// HMMA GEMM with 3-stage cp.async pipeline.
// C = A(split bf16) @ BT(split bf16)^T + bias, opt ReLU.
// 128x128 CTA tile, BK=32, 256 threads (4Mx2N warps, 32x64 warp tile).
// SMEM rows = 128B = [hi 64B | lo 64B], XOR swizzle, 3 stages x 32KB.
// ---------------------------------------------------------------------------
#define TBK 32
#define STAGE_BYTES 32768
#define NSTAGE 3
#define GEMM_SMEM_BYTES (NSTAGE * STAGE_BYTES)   // 96KB

__global__ __launch_bounds__(256, 1)
void gemm_tc_kernel(const __nv_bfloat16* __restrict__ Ah,
                    const __nv_bfloat16* __restrict__ Al,
                    const __nv_bfloat16* __restrict__ BTh,
                    const __nv_bfloat16* __restrict__ BTl,
                    const float* __restrict__ bias,
                    float* __restrict__ Cf,
                    __nv_bfloat16* __restrict__ Ch,
                    __nv_bfloat16* __restrict__ Cl,
                    int M, int N, int K, int relu)
{
    extern __shared__ char smem[];
    const uint32_t sb = smem_u32(smem);

    const int tid = threadIdx.x;
    const int wid = tid >> 5;
    const int lane = tid & 31;
    const int row0 = blockIdx.y * 128;
    const int col0 = blockIdx.x * 128;
    const int wm0 = (wid & 3) * 32;
    const int wn0 = (wid >> 2) * 64;
    const int nkb = K / TBK;

    // staging coords: each thread copies 4 A-chunks + 4 B-chunks (16B) per stage
    const int sr = tid >> 3;              // base row 0..31 (+ it*32)
    const int sj = tid & 7;               // chunk 0..7 (0-3 hi, 4-7 lo)
    const __nv_bfloat16* Asrc = (sj < 4) ? Ah : Al;
    const __nv_bfloat16* Bsrc = (sj < 4) ? BTh : BTl;
    const int sk = (sj & 3) * 8;

    // compute-lane coords
    const int lr = lane & 7;
    const int mh = (lane >> 3) & 1;
    const int kh = (lane >> 4) & 1;
    uint32_t aRow[2], bN[4];
#pragma unroll
    for (int mt = 0; mt < 2; mt++) aRow[mt] = wm0 + mt * 16 + mh * 8 + lr;
#pragma unroll
    for (int g = 0; g < 4; g++)    bN[g]   = wn0 + g * 16 + kh * 8 + lr;

    float acc[2][8][4];
#pragma unroll
    for (int mt = 0; mt < 2; mt++)
#pragma unroll
        for (int nt = 0; nt < 8; nt++)
#pragma unroll
            for (int i = 0; i < 4; i++) acc[mt][nt][i] = 0.f;

    auto issue = [&](int kb) {
        const int s = kb % NSTAGE;
        const uint32_t Ab = sb + s * STAGE_BYTES;
        const uint32_t Bb = Ab + 16384;
#pragma unroll
        for (int it = 0; it < 4; it++) {
            const int r = sr + it * 32;
            const uint32_t off = r * 128 + ((sj ^ (r & 7)) << 4);
            cp_async16(Ab + off, Asrc + (size_t)(row0 + r) * K + kb * TBK + sk);
            cp_async16(Bb + off, Bsrc + (size_t)(col0 + r) * K + kb * TBK + sk);
        }
    };
    auto compute = [&](int s) {
        const uint32_t Ab = sb + s * STAGE_BYTES;
        const uint32_t Bb = Ab + 16384;
#pragma unroll
        for (int kc = 0; kc < 2; kc++) {
            uint32_t ah[2][4], al[2][4];
#pragma unroll
            for (int mt = 0; mt < 2; mt++) {
                const uint32_t ra = Ab + aRow[mt] * 128;
                const int sw = aRow[mt] & 7;
                ldsm4(ah[mt], ra + (((kc * 2 + kh    ) ^ sw) << 4));
                ldsm4(al[mt], ra + (((kc * 2 + kh + 4) ^ sw) << 4));
            }
#pragma unroll
            for (int g = 0; g < 4; g++) {
                const uint32_t rb = Bb + bN[g] * 128;
                const int sw = bN[g] & 7;
                uint32_t bh[4], bl[4];
                ldsm4(bh, rb + (((kc * 2 + mh    ) ^ sw) << 4));
                ldsm4(bl, rb + (((kc * 2 + mh + 4) ^ sw) << 4));
#pragma unroll
                for (int mt = 0; mt < 2; mt++) {
                    mma16816(acc[mt][2 * g],     ah[mt], bh);
                    mma16816(acc[mt][2 * g + 1], ah[mt], bh + 2);
                    mma16816(acc[mt][2 * g],     ah[mt], bl);
                    mma16816(acc[mt][2 * g + 1], ah[mt], bl + 2);
                    mma16816(acc[mt][2 * g],     al[mt], bh);
                    mma16816(acc[mt][2 * g + 1], al[mt], bh + 2);
                }
            }
        }
    };

    // ---- 3-stage pipelined mainloop ----
    issue(0); cp_commit();
    issue(1); cp_commit();
    for (int kb = 0; kb < nkb; kb++) {
        if (kb + 1 < nkb) cp_wait<1>(); else cp_wait<0>();
        __syncthreads();
        if (kb + 2 < nkb) { issue(kb + 2); cp_commit(); }
        compute(kb % NSTAGE);
    }

    // epilogue
    const int qr = lane >> 2;
    const int qc = (lane & 3) * 2;
#pragma unroll
    for (int mt = 0; mt < 2; mt++) {
#pragma unroll
        for (int nt = 0; nt < 8; nt++) {
            const int r = row0 + wm0 + mt * 16 + qr;
            const int c = col0 + wn0 + nt * 8 + qc;
            const float b0 = bias[c], b1 = bias[c + 1];
            float v0 = acc[mt][nt][0] + b0;
            float v1 = acc[mt][nt][1] + b1;
            float v2 = acc[mt][nt][2] + b0;
            float v3 = acc[mt][nt][3] + b1;
            if (relu) {
                v0 = fmaxf(v0, 0.f); v1 = fmaxf(v1, 0.f);
                v2 = fmaxf(v2, 0.f); v3 = fmaxf(v3, 0.f);
            }
            if (Cf) {
                *(float2*)(Cf + (size_t)r * N + c) = make_float2(v0, v1);
                *(float2*)(Cf + (size_t)(r + 8) * N + c) = make_float2(v2, v3);
            }
            if (Ch) {
                uint32_t h0 = packbf(v0, v1);
                uint32_t h1 = packbf(v2, v3);
                float2 f0 = unpackbf(h0), f1 = unpackbf(h1);
                uint32_t l0 = packbf(v0 - f0.x, v1 - f0.y);
                uint32_t l1 = packbf(v2 - f1.x, v3 - f1.y);
                *(uint32_t*)((char*)Ch + ((size_t)r * N + c) * 2) = h0;
                *(uint32_t*)((char*)Ch + ((size_t)(r + 8) * N + c) * 2) = h1;
                *(uint32_t*)((char*)Cl + ((size_t)r * N + c) * 2) = l0;
                *(uint32_t*)((char*)Cl + ((size_t)(r + 8) * N + c) * 2) = l1;
            }
        }
    }
}

// ---------------------------------------------------------------------------
// Flash-attention with HMMA (split-3 bf16, fp32 accum), cp.async staging.
// CTA: (b, h, 128 q rows). 8 warps x 16 rows. 64-key blocks, 2-stage K/V.
// smem: Q 32KB + K 2x16KB + V 2x16KB = 96KB.
// ---------------------------------------------------------------------------
#define ATTN_SMEM 98304

__global__ __launch_bounds__(256, 1)
void attn_tc_kernel(const __nv_bfloat16* __restrict__ qh, const __nv_bfloat16* __restrict__ ql,
                    const __nv_bfloat16* __restrict__ kh_g, const __nv_bfloat16* __restrict__ kl_g,
                    const __nv_bfloat16* __restrict__ vh_g, const __nv_bfloat16* __restrict__ vl_g,
                    __nv_bfloat16* __restrict__ oh, __nv_bfloat16* __restrict__ ol, int L)
{
    extern __shared__ char smem[];
    const uint32_t sb = smem_u32(smem);
    const uint32_t qoff = sb;
    const uint32_t koff = sb + 32768;
    const uint32_t voff = sb + 65536;

    const int tid = threadIdx.x;
    const int wid = tid >> 5;
    const int lane = tid & 31;
    const int bh = blockIdx.y;
    const int b = bh / HEADS;
    const int hd = (bh % HEADS) * HEAD_DIM;
    const int l0 = blockIdx.x * 128;
    const int tok0 = b * L + l0;
    const int kbase = b * L;

    const int lr = lane & 7;
    const int mh = (lane >> 3) & 1;
    const int khb = (lane >> 4) & 1;

    auto issueKV = [&](int kb) {
        const int t0 = kbase + kb * 64;
        const int s = kb & 1;
        const uint32_t kb_ = koff + s * 16384;
        const uint32_t vb_ = voff + s * 16384;
#pragma unroll
        for (int it = 0; it < 4; it++) {
            int id = it * 256 + tid;
            {
                int c = id >> 9, row = (id >> 3) & 63, j = id & 7;
                const __nv_bfloat16* src = (j < 4) ? kh_g : kl_g;
                cp_async16(kb_ + c * 8192 + row * 128 + ((j ^ (row & 7)) << 4),
                           src + (size_t)(t0 + row) * D_MODEL + hd + c * 32 + (j & 3) * 8);
            }
            {
                int row = (id >> 3) & 63, j = id & 7;
                const __nv_bfloat16* src = (id < 512) ? vh_g : vl_g;
                cp_async16(vb_ + ((id < 512) ? 0 : 8192) + row * 128 + ((j ^ (row & 7)) << 4),
                           src + (size_t)(t0 + row) * D_MODEL + hd + j * 8);
            }
        }
    };

    // ---- Q tile + KV(0) via cp.async ----
#pragma unroll
    for (int it = 0; it < 8; it++) {
        int id = it * 256 + tid;
        int c = id >> 10, rem = id & 1023;
        int row = rem >> 3, j = rem & 7;
        const __nv_bfloat16* src = (j < 4) ? qh : ql;
        cp_async16(qoff + c * 16384 + row * 128 + ((j ^ (row & 7)) << 4),
                   src + (size_t)(tok0 + row) * D_MODEL + hd + c * 32 + (j & 3) * 8);
    }
    cp_commit();
    issueKV(0); cp_commit();
    cp_wait<0>();
    __syncthreads();

    // ---- preload Q fragments (4 k16 steps, hi+lo) ----
    uint32_t qah[4][4], qal[4][4];
    {
        const int aRow = wid * 16 + mh * 8 + lr;
        const int sw = aRow & 7;
#pragma unroll
        for (int c = 0; c < 2; c++) {
#pragma unroll
            for (int kc = 0; kc < 2; kc++) {
                const int t = c * 2 + kc;
                const uint32_t base = qoff + c * 16384 + aRow * 128;
                ldsm4(qah[t], base + (((kc * 2 + khb    ) ^ sw) << 4));
                ldsm4(qal[t], base + (((kc * 2 + khb + 4) ^ sw) << 4));
            }
        }
    }

    float m0 = -3.0e38f, m1 = -3.0e38f, li0 = 0.f, li1 = 0.f;
    float oacc[8][4];
#pragma unroll
    for (int j = 0; j < 8; j++)
#pragma unroll
        for (int i = 0; i < 4; i++) oacc[j][i] = 0.f;

    const int nkb = L / 64;
    for (int kb = 0; kb < nkb; kb++) {
        const int s = kb & 1;
        if (kb) {
            cp_wait<0>();
            __syncthreads();
        }
        if (kb + 1 < nkb) { issueKV(kb + 1); cp_commit(); }

        // ---- S = Q @ K^T (split-3) ----
        float sacc[8][4];
#pragma unroll
        for (int j = 0; j < 8; j++)
#pragma unroll
            for (int i = 0; i < 4; i++) sacc[j][i] = 0.f;

        const uint32_t kst = koff + s * 16384;
#pragma unroll
        for (int g = 0; g < 4; g++) {
            const int bN = g * 16 + khb * 8 + lr;
            const int sw = bN & 7;
#pragma unroll
            for (int c = 0; c < 2; c++) {
                const uint32_t rb = kst + c * 8192 + bN * 128;
#pragma unroll
                for (int kc = 0; kc < 2; kc++) {
                    const int t = c * 2 + kc;
                    uint32_t bh4[4], bl4[4];
                    ldsm4(bh4, rb + (((kc * 2 + mh    ) ^ sw) << 4));
                    ldsm4(bl4, rb + (((kc * 2 + mh + 4) ^ sw) << 4));
                    mma16816(sacc[2 * g],     qah[t], bh4);
                    mma16816(sacc[2 * g + 1], qah[t], bh4 + 2);
                    mma16816(sacc[2 * g],     qah[t], bl4);
                    mma16816(sacc[2 * g + 1], qah[t], bl4 + 2);
                    mma16816(sacc[2 * g],     qal[t], bh4);
                    mma16816(sacc[2 * g + 1], qal[t], bh4 + 2);
                }
            }
        }

        // ---- online softmax ----
#pragma unroll
        for (int j = 0; j < 8; j++)
#pragma unroll
            for (int i = 0; i < 4; i++) sacc[j][i] *= 0.125f;

        float mx0 = -3.0e38f, mx1 = -3.0e38f;
#pragma unroll
        for (int j = 0; j < 8; j++) {
            mx0 = fmaxf(mx0, fmaxf(sacc[j][0], sacc[j][1]));
            mx1 = fmaxf(mx1, fmaxf(sacc[j][2], sacc[j][3]));
        }
        mx0 = fmaxf(mx0, __shfl_xor_sync(0xffffffffu, mx0, 1));
        mx0 = fmaxf(mx0, __shfl_xor_sync(0xffffffffu, mx0, 2));
        mx1 = fmaxf(mx1, __shfl_xor_sync(0xffffffffu, mx1, 1));
        mx1 = fmaxf(mx1, __shfl_xor_sync(0xffffffffu, mx1, 2));
        const float mn0 = fmaxf(m0, mx0);
        const float mn1 = fmaxf(m1, mx1);
        const float co0 = __expf(m0 - mn0);
        const float co1 = __expf(m1 - mn1);
        float rs0 = 0.f, rs1 = 0.f;
#pragma unroll
        for (int j = 0; j < 8; j++) {
            sacc[j][0] = __expf(sacc[j][0] - mn0);
            sacc[j][1] = __expf(sacc[j][1] - mn0);
            sacc[j][2] = __expf(sacc[j][2] - mn1);
            sacc[j][3] = __expf(sacc[j][3] - mn1);
            rs0 += sacc[j][0] + sacc[j][1];
            rs1 += sacc[j][2] + sacc[j][3];
        }
        rs0 += __shfl_xor_sync(0xffffffffu, rs0, 1);
        rs0 += __shfl_xor_sync(0xffffffffu, rs0, 2);
        rs1 += __shfl_xor_sync(0xffffffffu, rs1, 1);
        rs1 += __shfl_xor_sync(0xffffffffu, rs1, 2);
        li0 = li0 * co0 + rs0;
        li1 = li1 * co1 + rs1;
        m0 = mn0; m1 = mn1;
#pragma unroll
        for (int j = 0; j < 8; j++) {
            oacc[j][0] *= co0; oacc[j][1] *= co0;
            oacc[j][2] *= co1; oacc[j][3] *= co1;
        }

        // ---- O += P @ V (split-3; V via ldmatrix.trans) ----
        const uint32_t vst = voff + s * 16384;
#pragma unroll
        for (int t = 0; t < 4; t++) {
            const int j0 = 2 * t, j1 = 2 * t + 1;
            uint32_t ph[4], pl[4];
            ph[0] = packbf(sacc[j0][0], sacc[j0][1]);
            ph[1] = packbf(sacc[j0][2], sacc[j0][3]);
            ph[2] = packbf(sacc[j1][0], sacc[j1][1]);
            ph[3] = packbf(sacc[j1][2], sacc[j1][3]);
#pragma unroll
            for (int i = 0; i < 4; i++) {
                float2 f = unpackbf(ph[i]);
                const float* sp = (i < 2) ? sacc[j0] : sacc[j1];
                int o = (i & 1) * 2;
                pl[i] = packbf(sp[o] - f.x, sp[o + 1] - f.y);
            }
            const int vRow = t * 16 + mh * 8 + lr;
            const int sw = vRow & 7;
            const uint32_t vrb = vst + vRow * 128;
#pragma unroll
            for (int g = 0; g < 4; g++) {
                uint32_t vh4[4], vl4[4];
                ldsm4t(vh4, vrb + (((g * 2 + khb) ^ sw) << 4));
                ldsm4t(vl4, vrb + 8192 + (((g * 2 + khb) ^ sw) << 4));
                mma16816(oacc[2 * g],     ph, vh4);
                mma16816(oacc[2 * g + 1], ph, vh4 + 2);
                mma16816(oacc[2 * g],     ph, vl4);
                mma16816(oacc[2 * g + 1], ph, vl4 + 2);
                mma16816(oacc[2 * g],     pl, vh4);
                mma16816(oacc[2 * g + 1], pl, vh4 + 2);
            }
        }
    }

    // ---- epilogue: normalize, split, write ----
    const float inv0 = 1.f / li0;
    const float inv1 = 1.f / li1;
    const int r0 = tok0 + wid * 16 + (lane >> 2);
    const int r1 = r0 + 8;
#pragma unroll
    for (int j = 0; j < 8; j++) {
        const int c = hd + j * 8 + (lane & 3) * 2;
        float v0 = oacc[j][0] * inv0, v1 = oacc[j][1] * inv0;
        float v2 = oacc[j][2] * inv1, v3 = oacc[j][3] * inv1;
        uint32_t h0 = packbf(v0, v1), h1 = packbf(v2, v3);
        float2 f0 = unpackbf(h0), f1 = unpackbf(h1);
        uint32_t lo0 = packbf(v0 - f0.x, v1 - f0.y);
        uint32_t lo1 = packbf(v2 - f1.x, v3 - f1.y);
        *(uint32_t*)((char*)oh + ((size_t)r0 * D_MODEL + c) * 2) = h0;
        *(uint32_t*)((char*)ol + ((size_t)r0 * D_MODEL + c) * 2) = lo0;
        *(uint32_t*)((char*)oh + ((size_t)r1 * D_MODEL + c) * 2) = h1;
        *(uint32_t*)((char*)ol + ((size_t)r1 * D_MODEL + c) * 2) = lo1;
    }
}

// ---------------------------------------------------------------------------
// Fused residual + LayerNorm (+ optional split bf16 outputs)
// ---------------------------------------------------------------------------
__global__ __launch_bounds__(256) void ln_residual_kernel(
    const float* __restrict__ a, const float* __restrict__ r,
    const float* __restrict__ g, const float* __restrict__ beta,
    float* __restrict__ out, __nv_bfloat16* __restrict__ outh,
    __nv_bfloat16* __restrict__ outl)
{
    __shared__ float red[8];
    const int row = blockIdx.x;
    const int tid = threadIdx.x;
    const int lane = tid & 31, warp = tid >> 5;
    const size_t off = (size_t)row * D_MODEL + tid * 4;

    float4 va = *(const float4*)(a + off);
    float4 vr = *(const float4*)(r + off);
    float x[4] = {va.x + vr.x, va.y + vr.y, va.z + vr.z, va.w + vr.w};

    float sum = x[0] + x[1] + x[2] + x[3];
#pragma unroll
    for (int o = 16; o; o >>= 1) sum += __shfl_down_sync(0xffffffffu, sum, o);
    if (lane == 0) red[warp] = sum;
    __syncthreads();
    if (warp == 0) {
        float v = (lane < 8) ? red[lane] : 0.f;
#pragma unroll
        for (int o = 4; o; o >>= 1) v += __shfl_down_sync(0xffu, v, o);
        if (lane == 0) red[0] = v;
    }
    __syncthreads();
    const float mu = red[0] * (1.f / D_MODEL);
    __syncthreads();

    float sq = 0.f;
#pragma unroll
    for (int i = 0; i < 4; i++) {
        float d = x[i] - mu;
        sq += d * d;
    }
#pragma unroll
    for (int o = 16; o; o >>= 1) sq += __shfl_down_sync(0xffffffffu, sq, o);
    if (lane == 0) red[warp] = sq;
    __syncthreads();
    if (warp == 0) {
        float v = (lane < 8) ? red[lane] : 0.f;
#pragma unroll
        for (int o = 4; o; o >>= 1) v += __shfl_down_sync(0xffu, v, o);
        if (lane == 0) red[0] = v;
    }
    __syncthreads();
    const float rstd = rsqrtf(red[0] * (1.f / D_MODEL) + EPS);

    float4 gg = *(const float4*)(g + tid * 4);
    float4 bb = *(const float4*)(beta + tid * 4);
    float y[4];
    y[0] = (x[0] - mu) * rstd * gg.x + bb.x;
    y[1] = (x[1] - mu) * rstd * gg.y + bb.y;
    y[2] = (x[2] - mu) * rstd * gg.z + bb.z;
    y[3] = (x[3] - mu) * rstd * gg.w + bb.w;
    *(float4*)(out + off) = *(float4*)&y[0];
    if (outh) {
        uint32_t h0 = packbf(y[0], y[1]), h1 = packbf(y[2], y[3]);
        float2 f0 = unpackbf(h0), f1 = unpackbf(h1);
        uint32_t l0 = packbf(y[0] - f0.x, y[1] - f0.y);
        uint32_t l1 = packbf(y[2] - f1.x, y[3] - f1.y);
        *(uint2*)((char*)outh + off * 2) = make_uint2(h0, h1);
        *(uint2*)((char*)outl + off * 2) = make_uint2(l0, l1);
    }
}

// ---------------------------------------------------------------------------
// Launch sequence
// ---------------------------------------------------------------------------
extern "C" void kernel_launch(void* const* d_in, const int* in_sizes, int n_in,
                              void* d_out, int out_size)
{
    const float* x  = (const float*)d_in[0];
    const float* Wq = (const float*)d_in[1];
    const float* bq = (const float*)d_in[2];
    const float* Wk = (const float*)d_in[3];
    const float* bk = (const float*)d_in[4];
    const float* Wv = (const float*)d_in[5];
    const float* bv = (const float*)d_in[6];
    const float* Wm = (const float*)d_in[7];
    const float* bm = (const float*)d_in[8];
    const float* W1 = (const float*)d_in[9];
    const float* b1 = (const float*)d_in[10];
    const float* W2 = (const float*)d_in[11];
    const float* b2 = (const float*)d_in[12];
    const float* g1  = (const float*)d_in[13];
    const float* be1 = (const float*)d_in[14];
    const float* g2  = (const float*)d_in[15];
    const float* be2 = (const float*)d_in[16];
    float* out = (float*)d_out;

    const int M = in_sizes[0] / D_MODEL;   // 4096
    const int L = SEQ_L;
    const int B = M / L;

    float *proj, *h, *tmp;
    cudaGetSymbolAddress((void**)&proj, g_proj);
    cudaGetSymbolAddress((void**)&h,    g_h);
    cudaGetSymbolAddress((void**)&tmp,  g_tmp);

    __nv_bfloat16 *xh, *xl, *qh, *ql, *kh, *kl, *vh, *vl, *ah, *al, *hh, *hl, *ffh, *ffl;
    cudaGetSymbolAddress((void**)&xh, g_xh); cudaGetSymbolAddress((void**)&xl, g_xl);
    cudaGetSymbolAddress((void**)&qh, g_qh); cudaGetSymbolAddress((void**)&ql, g_ql);
    cudaGetSymbolAddress((void**)&kh, g_kh); cudaGetSymbolAddress((void**)&kl, g_kl);
    cudaGetSymbolAddress((void**)&vh, g_vh); cudaGetSymbolAddress((void**)&vl, g_vl);
    cudaGetSymbolAddress((void**)&ah, g_ah); cudaGetSymbolAddress((void**)&al, g_al);
    cudaGetSymbolAddress((void**)&hh, g_hh); cudaGetSymbolAddress((void**)&hl, g_hl);
    cudaGetSymbolAddress((void**)&ffh, g_ffh); cudaGetSymbolAddress((void**)&ffl, g_ffl);

    __nv_bfloat16 *wqh, *wql, *wkh, *wkl, *wvh, *wvl, *wmh, *wml, *w1h, *w1l, *w2h, *w2l;
    cudaGetSymbolAddress((void**)&wqh, g_wq_h); cudaGetSymbolAddress((void**)&wql, g_wq_l);
    cudaGetSymbolAddress((void**)&wkh, g_wk_h); cudaGetSymbolAddress((void**)&wkl, g_wk_l);
    cudaGetSymbolAddress((void**)&wvh, g_wv_h); cudaGetSymbolAddress((void**)&wvl, g_wv_l);
    cudaGetSymbolAddress((void**)&wmh, g_wm_h); cudaGetSymbolAddress((void**)&wml, g_wm_l);
    cudaGetSymbolAddress((void**)&w1h, g_w1_h); cudaGetSymbolAddress((void**)&w1l, g_w1_l);
    cudaGetSymbolAddress((void**)&w2h, g_w2_h); cudaGetSymbolAddress((void**)&w2l, g_w2_l);

    static bool attr_set = false;
    if (!attr_set) {
        cudaFuncSetAttribute(gemm_tc_kernel,
                             cudaFuncAttributeMaxDynamicSharedMemorySize, GEMM_SMEM_BYTES);
        cudaFuncSetAttribute(attn_tc_kernel,
                             cudaFuncAttributeMaxDynamicSharedMemorySize, ATTN_SMEM);
        attr_set = true;
    }

    dim3 blk(256);

    // prep: weight transpose+split, x split
    transpose_split_kernel<<<dim3(D_MODEL / 32, D_MODEL / 32), blk>>>(Wq, wqh, wql, D_MODEL, D_MODEL);
    transpose_split_kernel<<<dim3(D_MODEL / 32, D_MODEL / 32), blk>>>(Wk, wkh, wkl, D_MODEL, D_MODEL);
    transpose_split_kernel<<<dim3(D_MODEL / 32, D_MODEL / 32), blk>>>(Wv, wvh, wvl, D_MODEL, D_MODEL);
    transpose_split_kernel<<<dim3(D_MODEL / 32, D_MODEL / 32), blk>>>(Wm, wmh, wml, D_MODEL, D_MODEL);
    transpose_split_kernel<<<dim3(FF_DIM / 32, D_MODEL / 32), blk>>>(W1, w1h, w1l, D_MODEL, FF_DIM);
    transpose_split_kernel<<<dim3(D_MODEL / 32, FF_DIM / 32), blk>>>(W2, w2h, w2l, FF_DIM, D_MODEL);
    split_kernel<<<(M * D_MODEL / 4 + 255) / 256, blk>>>(x, xh, xl, M * D_MODEL / 4);

    dim3 grid_d(D_MODEL / 128, M / 128);   // (8, 32)
    dim3 grid_f(FF_DIM / 128,  M / 128);   // (32, 32)

    // QKV projections -> split bf16 only
    gemm_tc_kernel<<<grid_d, blk, GEMM_SMEM_BYTES>>>(xh, xl, wqh, wql, bq, nullptr, qh, ql, M, D_MODEL, D_MODEL, 0);
    gemm_tc_kernel<<<grid_d, blk, GEMM_SMEM_BYTES>>>(xh, xl, wkh, wkl, bk, nullptr, kh, kl, M, D_MODEL, D_MODEL, 0);
    gemm_tc_kernel<<<grid_d, blk, GEMM_SMEM_BYTES>>>(xh, xl, wvh, wvl, bv, nullptr, vh, vl, M, D_MODEL, D_MODEL, 0);

    // attention (HMMA) -> split bf16
    dim3 agrid(L / 128, B * HEADS);        // (16, 32)
    attn_tc_kernel<<<agrid, blk, ATTN_SMEM>>>(qh, ql, kh, kl, vh, vl, ah, al, L);

    // output projection (fp32) + residual LN -> h fp32 + split
    gemm_tc_kernel<<<grid_d, blk, GEMM_SMEM_BYTES>>>(ah, al, wmh, wml, bm, proj, nullptr, nullptr, M, D_MODEL, D_MODEL, 0);
    ln_residual_kernel<<<M, blk>>>(x, proj, g1, be1, h, hh, hl);

    // FFN
    gemm_tc_kernel<<<grid_f, blk, GEMM_SMEM_BYTES>>>(hh, hl, w1h, w1l, b1, nullptr, ffh, ffl, M, FF_DIM, D_MODEL, 1);
    gemm_tc_kernel<<<grid_d, blk, GEMM_SMEM_BYTES>>>(ffh, ffl, w2h, w2l, b2, tmp, nullptr, nullptr, M, D_MODEL, FF_DIM, 0);
    ln_residual_kernel<<<M, blk>>>(h, tmp, g2, be2, out, nullptr, nullptr);
}